// round 4
// baseline (speedup 1.0000x reference)
#include <cuda_runtime.h>
#include <cuda_bf16.h>

// Problem constants
#define BB   4
#define LL   2048
#define AD   1024      // ATTEN_DIM == Q_DIM == K_DIM == V_DIM
#define NH   16
#define HD   64        // head dim
#define MM   (BB*LL)   // 8192 rows for all GEMMs

// ---------------------------------------------------------------------------
// Scratch (device globals — no runtime allocation allowed)
// ---------------------------------------------------------------------------
__device__ float g_q  [MM * AD];
__device__ float g_k  [MM * AD];
__device__ float g_v  [MM * AD];
__device__ float g_att[MM * AD];

// ---------------------------------------------------------------------------
// GEMM: C[M,N] = A[M,K] @ W[K,N] + bias   (K = N = 1024, M = 8192)
// 128x128 block, BK=8, 256 threads, 8x8 microtile (split 4+4 for bank spread)
// ---------------------------------------------------------------------------
__global__ __launch_bounds__(256, 2)
void gemm_bias_kernel(const float* __restrict__ A,
                      const float* __restrict__ W,
                      const float* __restrict__ bias,
                      float* __restrict__ C)
{
    constexpr int K = 1024;
    constexpr int N = 1024;
    constexpr int NT = K / 8;          // 128 k-tiles

    __shared__ float As[8][132];       // transposed A tile: As[k][m]
    __shared__ float Bs[8][132];       // Bs[k][n]

    const int tid = threadIdx.x;
    const int bm = blockIdx.y * 128;
    const int bn = blockIdx.x * 128;

    const int ty = tid >> 4;           // 0..15
    const int tx = tid & 15;           // 0..15

    // global load assignments
    const int a_row = tid >> 1;               // 0..127
    const int a_k   = (tid & 1) * 4;          // 0 or 4
    const int b_k   = tid >> 5;               // 0..7
    const int b_n   = (tid & 31) * 4;         // 0..124

    const float* Aptr = A + (bm + a_row) * K + a_k;
    const float* Wptr = W + b_k * N + bn + b_n;

    float4 pa = *reinterpret_cast<const float4*>(Aptr);
    float4 pb = *reinterpret_cast<const float4*>(Wptr);

    float acc[8][8];
#pragma unroll
    for (int i = 0; i < 8; ++i)
#pragma unroll
        for (int j = 0; j < 8; ++j) acc[i][j] = 0.f;

    for (int t = 0; t < NT; ++t) {
        // commit prefetched tile to smem
        As[a_k + 0][a_row] = pa.x;
        As[a_k + 1][a_row] = pa.y;
        As[a_k + 2][a_row] = pa.z;
        As[a_k + 3][a_row] = pa.w;
        *reinterpret_cast<float4*>(&Bs[b_k][b_n]) = pb;
        __syncthreads();

        if (t + 1 < NT) {
            pa = *reinterpret_cast<const float4*>(Aptr + (t + 1) * 8);
            pb = *reinterpret_cast<const float4*>(Wptr + (t + 1) * 8 * N);
        }

#pragma unroll
        for (int k = 0; k < 8; ++k) {
            float4 a0 = *reinterpret_cast<const float4*>(&As[k][ty * 4]);
            float4 a1 = *reinterpret_cast<const float4*>(&As[k][64 + ty * 4]);
            float4 b0 = *reinterpret_cast<const float4*>(&Bs[k][tx * 4]);
            float4 b1 = *reinterpret_cast<const float4*>(&Bs[k][64 + tx * 4]);
            float ar[8] = {a0.x, a0.y, a0.z, a0.w, a1.x, a1.y, a1.z, a1.w};
            float br[8] = {b0.x, b0.y, b0.z, b0.w, b1.x, b1.y, b1.z, b1.w};
#pragma unroll
            for (int i = 0; i < 8; ++i)
#pragma unroll
                for (int j = 0; j < 8; ++j)
                    acc[i][j] += ar[i] * br[j];
        }
        __syncthreads();
    }

    // epilogue: bias + store
    float bb0[4], bb1[4];
#pragma unroll
    for (int j = 0; j < 4; ++j) {
        bb0[j] = bias[bn + tx * 4 + j];
        bb1[j] = bias[bn + 64 + tx * 4 + j];
    }
#pragma unroll
    for (int i = 0; i < 8; ++i) {
        int r = bm + ((i < 4) ? (ty * 4 + i) : (64 + ty * 4 + (i - 4)));
        float4 o0, o1;
        o0.x = acc[i][0] + bb0[0]; o0.y = acc[i][1] + bb0[1];
        o0.z = acc[i][2] + bb0[2]; o0.w = acc[i][3] + bb0[3];
        o1.x = acc[i][4] + bb1[0]; o1.y = acc[i][5] + bb1[1];
        o1.z = acc[i][6] + bb1[2]; o1.w = acc[i][7] + bb1[3];
        *reinterpret_cast<float4*>(&C[r * N + bn + tx * 4])      = o0;
        *reinterpret_cast<float4*>(&C[r * N + bn + 64 + tx * 4]) = o1;
    }
}

// ---------------------------------------------------------------------------
// Flash attention: one CTA per (q-tile of 64 rows, head, batch).
// 256 threads, 4x4 microtile on a 64x64 S/O tile. Online softmax.
// K tile stored transposed with XOR swizzle: phys word for (d, c) =
//   d*64 + (((c>>2) ^ (d>>2)) << 2) + (c&3)   -> conflict-free stores + reads.
// V tile reuses the K buffer (plain row-major).
// ---------------------------------------------------------------------------
__global__ __launch_bounds__(256, 2)
void attn_kernel(const float* __restrict__ Q,
                 const float* __restrict__ Kg,
                 const float* __restrict__ Vg,
                 float* __restrict__ Oatt)
{
    __shared__ float Qs[64 * 64];
    __shared__ float KV[64 * 64];
    __shared__ float Ss[64 * 64];

    const int qt = blockIdx.x;     // 0..31
    const int h  = blockIdx.y;     // 0..15
    const int b  = blockIdx.z;     // 0..3

    const int tid = threadIdx.x;
    const int ty = tid >> 4;       // 0..15
    const int tx = tid & 15;       // 0..15

    const int base = (b * LL) * AD + h * HD;   // element offset of row 0 of this (b,h)
    const int q0 = qt * 64;

    // ---- load Q tile (coalesced float4) ----
    {
        const int r  = tid >> 4;
        const int d4 = (tid & 15) * 4;
#pragma unroll
        for (int it = 0; it < 4; ++it) {
            int rr = r + it * 16;
            float4 v = *reinterpret_cast<const float4*>(Q + base + (q0 + rr) * AD + d4);
            *reinterpret_cast<float4*>(&Qs[rr * 64 + d4]) = v;
        }
    }

    float m[4], lsum[4], o[4][4];
#pragma unroll
    for (int i = 0; i < 4; ++i) {
        m[i] = -1e30f; lsum[i] = 0.f;
#pragma unroll
        for (int j = 0; j < 4; ++j) o[i][j] = 0.f;
    }

    for (int c0 = 0; c0 < LL; c0 += 64) {
        __syncthreads();   // prior chunk's PV reads done; Q load done (1st iter)

        // ---- load K chunk, transposed + swizzled into KV ----
        {
            const int d4 = (tid & 15) * 4;          // base row in Kts
            const int cg = tid >> 4;                // column, +16 per iter
#pragma unroll
            for (int it = 0; it < 4; ++it) {
                int cc = cg + it * 16;
                float4 v = *reinterpret_cast<const float4*>(Kg + base + (c0 + cc) * AD + d4);
                int pg = ((cc >> 2) ^ (tid & 15));  // (c/4) ^ (d/4)
                float* dst = &KV[d4 * 64 + pg * 4 + (cc & 3)];
                dst[0]   = v.x;
                dst[64]  = v.y;
                dst[128] = v.z;
                dst[192] = v.w;
            }
        }
        __syncthreads();

        // ---- S = Q @ K^T (scaled) ----
        float s[4][4];
#pragma unroll
        for (int i = 0; i < 4; ++i)
#pragma unroll
            for (int j = 0; j < 4; ++j) s[i][j] = 0.f;

#pragma unroll
        for (int dd = 0; dd < 16; ++dd) {
            float kr[4][4], qr[4][4];
#pragma unroll
            for (int lr = 0; lr < 4; ++lr) {
                float4 t = *reinterpret_cast<const float4*>(
                    &KV[(4 * dd + lr) * 64 + ((tx ^ dd) * 4)]);
                kr[lr][0] = t.x; kr[lr][1] = t.y; kr[lr][2] = t.z; kr[lr][3] = t.w;
            }
#pragma unroll
            for (int i = 0; i < 4; ++i) {
                float4 t = *reinterpret_cast<const float4*>(
                    &Qs[(4 * ty + i) * 64 + 4 * dd]);
                qr[i][0] = t.x; qr[i][1] = t.y; qr[i][2] = t.z; qr[i][3] = t.w;
            }
#pragma unroll
            for (int i = 0; i < 4; ++i)
#pragma unroll
                for (int j = 0; j < 4; ++j)
#pragma unroll
                    for (int lr = 0; lr < 4; ++lr)
                        s[i][j] += qr[i][lr] * kr[lr][j];
        }

        const float scale = 0.125f;   // 1/sqrt(64)
#pragma unroll
        for (int i = 0; i < 4; ++i)
#pragma unroll
            for (int j = 0; j < 4; ++j) s[i][j] *= scale;

        // ---- online softmax (16-lane half-warp reductions) ----
#pragma unroll
        for (int i = 0; i < 4; ++i) {
            float cm = fmaxf(fmaxf(s[i][0], s[i][1]), fmaxf(s[i][2], s[i][3]));
#pragma unroll
            for (int off = 1; off < 16; off <<= 1)
                cm = fmaxf(cm, __shfl_xor_sync(0xffffffffu, cm, off));
            float mn = fmaxf(m[i], cm);
            float corr = __expf(m[i] - mn);
            m[i] = mn;
            float p0 = __expf(s[i][0] - mn);
            float p1 = __expf(s[i][1] - mn);
            float p2 = __expf(s[i][2] - mn);
            float p3 = __expf(s[i][3] - mn);
            float rs = (p0 + p1) + (p2 + p3);
#pragma unroll
            for (int off = 1; off < 16; off <<= 1)
                rs += __shfl_xor_sync(0xffffffffu, rs, off);
            lsum[i] = lsum[i] * corr + rs;
#pragma unroll
            for (int j = 0; j < 4; ++j) o[i][j] *= corr;
            float4 pv = make_float4(p0, p1, p2, p3);
            *reinterpret_cast<float4*>(&Ss[(4 * ty + i) * 64 + tx * 4]) = pv;
        }

        __syncthreads();   // all P written, all K reads done

        // ---- load V chunk (plain row-major, reuses KV) ----
        {
            const int kr = tid >> 4;
            const int c4 = (tid & 15) * 4;
#pragma unroll
            for (int it = 0; it < 4; ++it) {
                int kk = kr + it * 16;
                float4 v = *reinterpret_cast<const float4*>(Vg + base + (c0 + kk) * AD + c4);
                *reinterpret_cast<float4*>(&KV[kk * 64 + c4]) = v;
            }
        }
        __syncthreads();

        // ---- O += P @ V ----
#pragma unroll
        for (int k4 = 0; k4 < 16; ++k4) {
            float vr[4][4], pr[4][4];
#pragma unroll
            for (int lr = 0; lr < 4; ++lr) {
                float4 t = *reinterpret_cast<const float4*>(
                    &KV[(4 * k4 + lr) * 64 + tx * 4]);
                vr[lr][0] = t.x; vr[lr][1] = t.y; vr[lr][2] = t.z; vr[lr][3] = t.w;
            }
#pragma unroll
            for (int i = 0; i < 4; ++i) {
                float4 t = *reinterpret_cast<const float4*>(
                    &Ss[(4 * ty + i) * 64 + k4 * 4]);
                pr[i][0] = t.x; pr[i][1] = t.y; pr[i][2] = t.z; pr[i][3] = t.w;
            }
#pragma unroll
            for (int i = 0; i < 4; ++i)
#pragma unroll
                for (int j = 0; j < 4; ++j)
#pragma unroll
                    for (int lr = 0; lr < 4; ++lr)
                        o[i][j] += pr[i][lr] * vr[lr][j];
        }
    }

    // ---- normalize + store ----
#pragma unroll
    for (int i = 0; i < 4; ++i) {
        float inv = 1.f / lsum[i];
        float4 r = make_float4(o[i][0] * inv, o[i][1] * inv,
                               o[i][2] * inv, o[i][3] * inv);
        *reinterpret_cast<float4*>(
            Oatt + base + (q0 + 4 * ty + i) * AD + tx * 4) = r;
    }
}

// ---------------------------------------------------------------------------
// Launch
// ---------------------------------------------------------------------------
extern "C" void kernel_launch(void* const* d_in, const int* in_sizes, int n_in,
                              void* d_out, int out_size)
{
    const float* query = (const float*)d_in[0];
    const float* key   = (const float*)d_in[1];
    const float* value = (const float*)d_in[2];
    const float* Wq = (const float*)d_in[3];
    const float* bq = (const float*)d_in[4];
    const float* Wk = (const float*)d_in[5];
    const float* bk = (const float*)d_in[6];
    const float* Wv = (const float*)d_in[7];
    const float* bv = (const float*)d_in[8];
    const float* Wo = (const float*)d_in[9];
    const float* bo = (const float*)d_in[10];
    float* out = (float*)d_out;

    float *pq, *pk, *pv, *patt;
    cudaGetSymbolAddress((void**)&pq,   g_q);
    cudaGetSymbolAddress((void**)&pk,   g_k);
    cudaGetSymbolAddress((void**)&pv,   g_v);
    cudaGetSymbolAddress((void**)&patt, g_att);

    dim3 ggrid(AD / 128, MM / 128);   // (8, 64)
    gemm_bias_kernel<<<ggrid, 256>>>(query, Wq, bq, pq);
    gemm_bias_kernel<<<ggrid, 256>>>(key,   Wk, bk, pk);
    gemm_bias_kernel<<<ggrid, 256>>>(value, Wv, bv, pv);

    dim3 agrid(LL / 64, NH, BB);      // (32, 16, 4)
    attn_kernel<<<agrid, 256>>>(pq, pk, pv, patt);

    gemm_bias_kernel<<<ggrid, 256>>>(patt, Wo, bo, out);
}

// round 6
// speedup vs baseline: 1.3886x; 1.3886x over previous
#include <cuda_runtime.h>
#include <cuda_bf16.h>
#include <cstdint>

// Problem constants
#define BB   4
#define LL   2048
#define AD   1024      // ATTEN_DIM == Q_DIM == K_DIM == V_DIM
#define NH   16
#define HD   64        // head dim
#define MM   (BB*LL)   // 8192 rows for all GEMMs
#define KX   3072      // expanded K for bf16 hi/lo split (hi|hi|lo vs hi|lo|hi)

// ---------------------------------------------------------------------------
// Scratch (device globals — no runtime allocation allowed)
// ---------------------------------------------------------------------------
__device__ float         g_q  [MM * AD];
__device__ float         g_k  [MM * AD];
__device__ float         g_v  [MM * AD];
__device__ __nv_bfloat16 g_hl [MM * KX];           // activation hi|hi|lo buffer (reused)
__device__ __nv_bfloat16 g_wt [4][AD * KX];        // Wq,Wk,Wv,Wo transposed hi|lo|hi

// ---------------------------------------------------------------------------
// Helpers (all instructions legal on plain sm_103: cp.async, ldmatrix, mma.sync)
// ---------------------------------------------------------------------------
__device__ __forceinline__ uint32_t smem_u32(const void* p) {
    uint32_t a;
    asm("{ .reg .u64 t; cvta.to.shared.u64 t, %1; cvt.u32.u64 %0, t; }" : "=r"(a) : "l"(p));
    return a;
}
#define CP_COMMIT()  asm volatile("cp.async.commit_group;" ::: "memory")
#define CP_WAIT(n)   asm volatile("cp.async.wait_group %0;" :: "n"(n) : "memory")

__device__ __forceinline__ uint32_t pack_bf16x2(__nv_bfloat16 a, __nv_bfloat16 b) {
    return (uint32_t)__bfloat16_as_ushort(a) | ((uint32_t)__bfloat16_as_ushort(b) << 16);
}
__device__ __forceinline__ void split_hl(float x, __nv_bfloat16& h, __nv_bfloat16& l) {
    h = __float2bfloat16_rn(x);
    l = __float2bfloat16_rn(x - __bfloat162float(h));
}

__device__ __forceinline__ void ldm_x4(uint32_t& r0, uint32_t& r1, uint32_t& r2, uint32_t& r3,
                                       uint32_t addr) {
    asm volatile("ldmatrix.sync.aligned.m8n8.x4.shared.b16 {%0,%1,%2,%3}, [%4];"
                 : "=r"(r0), "=r"(r1), "=r"(r2), "=r"(r3) : "r"(addr));
}
__device__ __forceinline__ void mma16816(float* d, const uint32_t* a, uint32_t b0, uint32_t b1) {
    asm volatile(
        "mma.sync.aligned.m16n8k16.row.col.f32.bf16.bf16.f32 "
        "{%0,%1,%2,%3}, {%4,%5,%6,%7}, {%8,%9}, {%0,%1,%2,%3};"
        : "+f"(d[0]), "+f"(d[1]), "+f"(d[2]), "+f"(d[3])
        : "r"(a[0]), "r"(a[1]), "r"(a[2]), "r"(a[3]), "r"(b0), "r"(b1));
}

// ---------------------------------------------------------------------------
// Conversion: activation fp32 [M,1024] -> bf16 [M,3072] laid out [hi | hi | lo]
// ---------------------------------------------------------------------------
__global__ void conv_act(const float* __restrict__ X, __nv_bfloat16* __restrict__ Y)
{
    int idx = blockIdx.x * blockDim.x + threadIdx.x;   // float4 index
    int m  = idx >> 8;
    int c  = (idx & 255) * 4;
    float4 v = *reinterpret_cast<const float4*>(X + m * AD + c);
    __nv_bfloat16 h0,h1,h2,h3,l0,l1,l2,l3;
    split_hl(v.x, h0, l0); split_hl(v.y, h1, l1);
    split_hl(v.z, h2, l2); split_hl(v.w, h3, l3);
    uint2 hp = make_uint2(pack_bf16x2(h0,h1), pack_bf16x2(h2,h3));
    uint2 lp = make_uint2(pack_bf16x2(l0,l1), pack_bf16x2(l2,l3));
    size_t base = (size_t)m * KX + c;
    *reinterpret_cast<uint2*>(Y + base)        = hp;
    *reinterpret_cast<uint2*>(Y + base + 1024) = hp;
    *reinterpret_cast<uint2*>(Y + base + 2048) = lp;
}

// ---------------------------------------------------------------------------
// Conversion: weight fp32 W[K=1024][N=1024] -> Wt bf16 [N=1024][K'=3072],
// layout along K': [hi | lo | hi]
// ---------------------------------------------------------------------------
__global__ void conv_wt(const float* __restrict__ W, __nv_bfloat16* __restrict__ Wt)
{
    __shared__ float s[32][33];
    int n0 = blockIdx.x * 32;
    int k0 = blockIdx.y * 32;
    int tx = threadIdx.x, ty = threadIdx.y;   // (32, 8)
#pragma unroll
    for (int i = 0; i < 4; ++i)
        s[ty + 8 * i][tx] = W[(k0 + ty + 8 * i) * AD + n0 + tx];
    __syncthreads();
#pragma unroll
    for (int i = 0; i < 4; ++i) {
        int n = n0 + ty + 8 * i;
        int k = k0 + tx;
        float x = s[tx][ty + 8 * i];
        __nv_bfloat16 h, l;
        split_hl(x, h, l);
        size_t base = (size_t)n * KX + k;
        Wt[base]        = h;
        Wt[base + 1024] = l;
        Wt[base + 2048] = h;
    }
}

// ---------------------------------------------------------------------------
// bf16 mma.sync GEMM: C[M,1024] = A'[M,3072] x Wt[1024,3072]^T + bias (fp32)
// CTA 128x128 tile, 8 warps (64x32 warp tiles), K chunks of 64,
// cp.async double buffer, SW128-swizzled smem (128B rows), ldmatrix.x4.
// ---------------------------------------------------------------------------
#define GK_NC 48                      // 3072 / 64
#define SA0   0
#define SA1   16384
#define SB0   32768
#define SB1   49152
#define G_SMEM 65536

__device__ __forceinline__ void load_tile_cp(uint32_t sbase, uint32_t soff,
                                             const __nv_bfloat16* __restrict__ g,
                                             int row0, int kc, int tid)
{
#pragma unroll
    for (int i = 0; i < 4; ++i) {
        int idx = i * 256 + tid;              // 1024 segments: 128 rows x 8
        int r = idx >> 3, seg = idx & 7;
        const char* src = (const char*)g + ((size_t)(row0 + r) * KX + kc) * 2 + seg * 16;
        uint32_t dst = sbase + soff + r * 128 + ((seg * 16) ^ ((r & 7) * 16));
        asm volatile("cp.async.cg.shared.global [%0], [%1], 16;" :: "r"(dst), "l"(src));
    }
}

__global__ __launch_bounds__(256, 2)
void gemm_mma(const __nv_bfloat16* __restrict__ A,
              const __nv_bfloat16* __restrict__ Bt,
              const float* __restrict__ bias,
              float* __restrict__ C)
{
    extern __shared__ char smem[];
    const uint32_t sbase = smem_u32(smem);
    const int tid  = threadIdx.x;
    const int warp = tid >> 5;
    const int lane = tid & 31;
    const int bn = blockIdx.x * 128;
    const int bm = blockIdx.y * 128;

    const int wm0 = (warp >> 2) * 64;   // 0 / 64
    const int wn0 = (warp & 3) * 32;    // 0 / 32 / 64 / 96

    float d[4][4][4];
#pragma unroll
    for (int im = 0; im < 4; ++im)
#pragma unroll
        for (int jt = 0; jt < 4; ++jt)
#pragma unroll
            for (int q = 0; q < 4; ++q) d[im][jt][q] = 0.f;

    // ldmatrix per-fragment row bases (swizzle folds to k ^ ((row&7)*16))
    // A: row = wm0 + im*16 + (lane&15); kbyte = kstep*32 + (lane>>4)*16
    uint32_t a_rb[4], a_sw[4];
#pragma unroll
    for (int im = 0; im < 4; ++im) {
        int row = wm0 + im * 16 + (lane & 15);
        a_rb[im] = row * 128;
        a_sw[im] = (row & 7) * 16;
    }
    const uint32_t a_kb = (lane >> 4) * 16;
    // B: row = wn0 + jn*16 + (lane&7) + ((lane>>4)<<3); kbyte = kstep*32 + ((lane>>3)&1)*16
    uint32_t b_rb[2], b_sw[2];
#pragma unroll
    for (int jn = 0; jn < 2; ++jn) {
        int row = wn0 + jn * 16 + (lane & 7) + ((lane >> 4) << 3);
        b_rb[jn] = row * 128;
        b_sw[jn] = (row & 7) * 16;
    }
    const uint32_t b_kb = ((lane >> 3) & 1) * 16;

    load_tile_cp(sbase, SA0, A,  bm, 0, tid);
    load_tile_cp(sbase, SB0, Bt, bn, 0, tid);
    CP_COMMIT();

    for (int i = 0; i < GK_NC; ++i) {
        const uint32_t aoff = (i & 1) ? SA1 : SA0;
        const uint32_t boff = (i & 1) ? SB1 : SB0;
        if (i + 1 < GK_NC) {
            load_tile_cp(sbase, (i & 1) ? SA0 : SA1, A,  bm, (i + 1) * 64, tid);
            load_tile_cp(sbase, (i & 1) ? SB0 : SB1, Bt, bn, (i + 1) * 64, tid);
            CP_COMMIT();
            CP_WAIT(1);
        } else {
            CP_WAIT(0);
        }
        __syncthreads();

#pragma unroll
        for (int ks = 0; ks < 4; ++ks) {
            const uint32_t kb = ks * 32;
            uint32_t af[4][4];
#pragma unroll
            for (int im = 0; im < 4; ++im)
                ldm_x4(af[im][0], af[im][1], af[im][2], af[im][3],
                       sbase + aoff + a_rb[im] + ((kb + a_kb) ^ a_sw[im]));
            uint32_t bf[4][2];
#pragma unroll
            for (int jn = 0; jn < 2; ++jn) {
                uint32_t r0, r1, r2, r3;
                ldm_x4(r0, r1, r2, r3,
                       sbase + boff + b_rb[jn] + ((kb + b_kb) ^ b_sw[jn]));
                bf[jn * 2][0] = r0; bf[jn * 2][1] = r1;
                bf[jn * 2 + 1][0] = r2; bf[jn * 2 + 1][1] = r3;
            }
#pragma unroll
            for (int im = 0; im < 4; ++im)
#pragma unroll
                for (int jt = 0; jt < 4; ++jt)
                    mma16816(d[im][jt], af[im], bf[jt][0], bf[jt][1]);
        }
        __syncthreads();
    }

    // epilogue: bias + fp32 store
#pragma unroll
    for (int jt = 0; jt < 4; ++jt) {
        const int c0 = bn + wn0 + jt * 8 + 2 * (lane & 3);
        float2 bb = *reinterpret_cast<const float2*>(bias + c0);
#pragma unroll
        for (int im = 0; im < 4; ++im) {
            const int r0 = bm + wm0 + im * 16 + (lane >> 2);
            float2 o0 = make_float2(d[im][jt][0] + bb.x, d[im][jt][1] + bb.y);
            float2 o1 = make_float2(d[im][jt][2] + bb.x, d[im][jt][3] + bb.y);
            *reinterpret_cast<float2*>(C + (size_t)r0 * AD + c0)       = o0;
            *reinterpret_cast<float2*>(C + (size_t)(r0 + 8) * AD + c0) = o1;
        }
    }
}

// ---------------------------------------------------------------------------
// Flash attention (fp32): one CTA per (128-row q tile, head, batch).
// 256 threads, 8x4 microtile on a 128x64 S/O tile (25% less LDS per FMA).
// K tile transposed + XOR-swizzled; V reuses the K buffer.
// Output written as bf16 hi|hi|lo into the [M,3072] activation buffer.
// ---------------------------------------------------------------------------
#define ATTN_SMEM ((8192 + 8192 + 4096) * 4)   // Qs + Ss + KV = 80 KB

__global__ __launch_bounds__(256, 2)
void attn_kernel(const float* __restrict__ Q,
                 const float* __restrict__ Kg,
                 const float* __restrict__ Vg,
                 __nv_bfloat16* __restrict__ Oatt)
{
    extern __shared__ float smf[];
    float* Qs = smf;            // 128 x 64
    float* Ss = smf + 8192;     // 128 x 64
    float* KV = smf + 16384;    // 64 x 64

    const int qt = blockIdx.x;     // 0..15
    const int h  = blockIdx.y;
    const int b  = blockIdx.z;

    const int tid = threadIdx.x;
    const int ty = tid >> 4;       // 0..15 -> 8 rows each
    const int tx = tid & 15;       // 0..15 -> 4 cols each

    const int base = (b * LL) * AD + h * HD;
    const int q0 = qt * 128;

    // ---- load Q tile (128 x 64, coalesced float4) ----
    {
        const int r  = tid >> 4;
        const int d4 = (tid & 15) * 4;
#pragma unroll
        for (int it = 0; it < 8; ++it) {
            int rr = r + it * 16;
            float4 v = *reinterpret_cast<const float4*>(Q + base + (q0 + rr) * AD + d4);
            *reinterpret_cast<float4*>(&Qs[rr * 64 + d4]) = v;
        }
    }

    float m[8], lsum[8], o[8][4];
#pragma unroll
    for (int i = 0; i < 8; ++i) {
        m[i] = -1e30f; lsum[i] = 0.f;
#pragma unroll
        for (int j = 0; j < 4; ++j) o[i][j] = 0.f;
    }

    for (int c0 = 0; c0 < LL; c0 += 64) {
        __syncthreads();   // prior PV reads done; Q load done (1st iter)

        // ---- load K chunk transposed + swizzled ----
        {
            const int d4 = (tid & 15) * 4;
            const int cg = tid >> 4;
#pragma unroll
            for (int it = 0; it < 4; ++it) {
                int cc = cg + it * 16;
                float4 v = *reinterpret_cast<const float4*>(Kg + base + (c0 + cc) * AD + d4);
                int pg = ((cc >> 2) ^ (tid & 15));
                float* dst = &KV[d4 * 64 + pg * 4 + (cc & 3)];
                dst[0] = v.x; dst[64] = v.y; dst[128] = v.z; dst[192] = v.w;
            }
        }
        __syncthreads();

        // ---- S = Q @ K^T ----
        float s[8][4];
#pragma unroll
        for (int i = 0; i < 8; ++i)
#pragma unroll
            for (int j = 0; j < 4; ++j) s[i][j] = 0.f;

#pragma unroll
        for (int dd = 0; dd < 16; ++dd) {
            float kr[4][4];
#pragma unroll
            for (int lr = 0; lr < 4; ++lr) {
                float4 t = *reinterpret_cast<const float4*>(
                    &KV[(4 * dd + lr) * 64 + ((tx ^ dd) * 4)]);
                kr[lr][0] = t.x; kr[lr][1] = t.y; kr[lr][2] = t.z; kr[lr][3] = t.w;
            }
#pragma unroll
            for (int i = 0; i < 8; ++i) {
                float4 t = *reinterpret_cast<const float4*>(
                    &Qs[(8 * ty + i) * 64 + 4 * dd]);
#pragma unroll
                for (int j = 0; j < 4; ++j)
                    s[i][j] += t.x * kr[0][j] + t.y * kr[1][j]
                             + t.z * kr[2][j] + t.w * kr[3][j];
            }
        }

        const float scale = 0.125f;   // 1/sqrt(64)
#pragma unroll
        for (int i = 0; i < 8; ++i)
#pragma unroll
            for (int j = 0; j < 4; ++j) s[i][j] *= scale;

        // ---- online softmax (16-lane half-warp reductions) ----
#pragma unroll
        for (int i = 0; i < 8; ++i) {
            float cm = fmaxf(fmaxf(s[i][0], s[i][1]), fmaxf(s[i][2], s[i][3]));
#pragma unroll
            for (int off = 1; off < 16; off <<= 1)
                cm = fmaxf(cm, __shfl_xor_sync(0xffffffffu, cm, off));
            float mn = fmaxf(m[i], cm);
            float corr = __expf(m[i] - mn);
            m[i] = mn;
            float p0 = __expf(s[i][0] - mn);
            float p1 = __expf(s[i][1] - mn);
            float p2 = __expf(s[i][2] - mn);
            float p3 = __expf(s[i][3] - mn);
            float rs = (p0 + p1) + (p2 + p3);
#pragma unroll
            for (int off = 1; off < 16; off <<= 1)
                rs += __shfl_xor_sync(0xffffffffu, rs, off);
            lsum[i] = lsum[i] * corr + rs;
#pragma unroll
            for (int j = 0; j < 4; ++j) o[i][j] *= corr;
            float4 pv = make_float4(p0, p1, p2, p3);
            *reinterpret_cast<float4*>(&Ss[(8 * ty + i) * 64 + tx * 4]) = pv;
        }

        __syncthreads();   // all P written, all K reads done

        // ---- load V chunk (row-major, reuses KV) ----
        {
            const int kr2 = tid >> 4;
            const int c4 = (tid & 15) * 4;
#pragma unroll
            for (int it = 0; it < 4; ++it) {
                int kk = kr2 + it * 16;
                float4 v = *reinterpret_cast<const float4*>(Vg + base + (c0 + kk) * AD + c4);
                *reinterpret_cast<float4*>(&KV[kk * 64 + c4]) = v;
            }
        }
        __syncthreads();

        // ---- O += P @ V ----
#pragma unroll
        for (int k4 = 0; k4 < 16; ++k4) {
            float vr[4][4];
#pragma unroll
            for (int lr = 0; lr < 4; ++lr) {
                float4 t = *reinterpret_cast<const float4*>(
                    &KV[(4 * k4 + lr) * 64 + tx * 4]);
                vr[lr][0] = t.x; vr[lr][1] = t.y; vr[lr][2] = t.z; vr[lr][3] = t.w;
            }
#pragma unroll
            for (int i = 0; i < 8; ++i) {
                float4 t = *reinterpret_cast<const float4*>(
                    &Ss[(8 * ty + i) * 64 + k4 * 4]);
#pragma unroll
                for (int j = 0; j < 4; ++j)
                    o[i][j] += t.x * vr[0][j] + t.y * vr[1][j]
                             + t.z * vr[2][j] + t.w * vr[3][j];
            }
        }
    }

    // ---- normalize + store as bf16 hi|hi|lo into [M, 3072] buffer ----
#pragma unroll
    for (int i = 0; i < 8; ++i) {
        float inv = 1.f / lsum[i];
        float x0 = o[i][0] * inv, x1 = o[i][1] * inv;
        float x2 = o[i][2] * inv, x3 = o[i][3] * inv;
        __nv_bfloat16 h0,h1,h2,h3,l0,l1,l2,l3;
        split_hl(x0, h0, l0); split_hl(x1, h1, l1);
        split_hl(x2, h2, l2); split_hl(x3, h3, l3);
        uint2 hp = make_uint2(pack_bf16x2(h0,h1), pack_bf16x2(h2,h3));
        uint2 lp = make_uint2(pack_bf16x2(l0,l1), pack_bf16x2(l2,l3));
        size_t mrow = (size_t)(b * LL + q0 + 8 * ty + i) * KX + h * HD + tx * 4;
        *reinterpret_cast<uint2*>(Oatt + mrow)        = hp;
        *reinterpret_cast<uint2*>(Oatt + mrow + 1024) = hp;
        *reinterpret_cast<uint2*>(Oatt + mrow + 2048) = lp;
    }
}

// ---------------------------------------------------------------------------
// Launch
// ---------------------------------------------------------------------------
extern "C" void kernel_launch(void* const* d_in, const int* in_sizes, int n_in,
                              void* d_out, int out_size)
{
    const float* query = (const float*)d_in[0];
    const float* key   = (const float*)d_in[1];
    const float* value = (const float*)d_in[2];
    const float* Wq = (const float*)d_in[3];
    const float* bq = (const float*)d_in[4];
    const float* Wk = (const float*)d_in[5];
    const float* bk = (const float*)d_in[6];
    const float* Wv = (const float*)d_in[7];
    const float* bv = (const float*)d_in[8];
    const float* Wo = (const float*)d_in[9];
    const float* bo = (const float*)d_in[10];
    float* out = (float*)d_out;

    float *pq, *pk, *pv;
    __nv_bfloat16 *phl, *pwt;
    cudaGetSymbolAddress((void**)&pq,  g_q);
    cudaGetSymbolAddress((void**)&pk,  g_k);
    cudaGetSymbolAddress((void**)&pv,  g_v);
    cudaGetSymbolAddress((void**)&phl, g_hl);
    cudaGetSymbolAddress((void**)&pwt, g_wt);

    cudaFuncSetAttribute(gemm_mma,   cudaFuncAttributeMaxDynamicSharedMemorySize, G_SMEM);
    cudaFuncSetAttribute(attn_kernel, cudaFuncAttributeMaxDynamicSharedMemorySize, ATTN_SMEM);

    __nv_bfloat16* wtq = pwt + 0 * (size_t)(AD * KX);
    __nv_bfloat16* wtk = pwt + 1 * (size_t)(AD * KX);
    __nv_bfloat16* wtv = pwt + 2 * (size_t)(AD * KX);
    __nv_bfloat16* wto = pwt + 3 * (size_t)(AD * KX);

    dim3 wgrid(32, 32), wblk(32, 8);
    conv_wt<<<wgrid, wblk>>>(Wq, wtq);
    conv_wt<<<wgrid, wblk>>>(Wk, wtk);
    conv_wt<<<wgrid, wblk>>>(Wv, wtv);
    conv_wt<<<wgrid, wblk>>>(Wo, wto);

    dim3 ggrid(AD / 128, MM / 128);   // (8, 64)

    conv_act<<<MM, 256>>>(query, phl);
    gemm_mma<<<ggrid, 256, G_SMEM>>>(phl, wtq, bq, pq);

    conv_act<<<MM, 256>>>(key, phl);
    gemm_mma<<<ggrid, 256, G_SMEM>>>(phl, wtk, bk, pk);

    conv_act<<<MM, 256>>>(value, phl);
    gemm_mma<<<ggrid, 256, G_SMEM>>>(phl, wtv, bv, pv);

    dim3 agrid(LL / 128, NH, BB);     // (16, 16, 4)
    attn_kernel<<<agrid, 256, ATTN_SMEM>>>(pq, pk, pv, phl);

    gemm_mma<<<ggrid, 256, G_SMEM>>>(phl, wto, bo, out);
}

// round 7
// speedup vs baseline: 2.6806x; 1.9305x over previous
#include <cuda_runtime.h>
#include <cuda_bf16.h>
#include <cstdint>

// Problem constants
#define BB   4
#define LL   2048
#define AD   1024
#define NH   16
#define HD   64
#define MM   (BB*LL)   // 8192
#define KX   3072      // expanded K for bf16 hi/lo split

// ---------------------------------------------------------------------------
// Scratch (device globals)
// ---------------------------------------------------------------------------
__device__ __nv_bfloat16 g_hl [MM * KX];        // activation hi|hi|lo (GEMM A)
__device__ __nv_bfloat16 g_wt [4][AD * KX];     // weights^T hi|lo|hi
// head-major bf16 planes: [(b*16+h)][2048][64]
__device__ __nv_bfloat16 g_qh[MM * AD], g_ql[MM * AD];
__device__ __nv_bfloat16 g_kh[MM * AD], g_kl[MM * AD];
__device__ __nv_bfloat16 g_vh[MM * AD], g_vl[MM * AD];

// ---------------------------------------------------------------------------
// Helpers (plain sm_103-legal: cp.async, ldmatrix, mma.sync)
// ---------------------------------------------------------------------------
__device__ __forceinline__ uint32_t smem_u32(const void* p) {
    uint32_t a;
    asm("{ .reg .u64 t; cvta.to.shared.u64 t, %1; cvt.u32.u64 %0, t; }" : "=r"(a) : "l"(p));
    return a;
}
#define CP_COMMIT()  asm volatile("cp.async.commit_group;" ::: "memory")
#define CP_WAIT(n)   asm volatile("cp.async.wait_group %0;" :: "n"(n) : "memory")

__device__ __forceinline__ uint32_t pack_bf16x2(__nv_bfloat16 a, __nv_bfloat16 b) {
    return (uint32_t)__bfloat16_as_ushort(a) | ((uint32_t)__bfloat16_as_ushort(b) << 16);
}
__device__ __forceinline__ void split_hl(float x, __nv_bfloat16& h, __nv_bfloat16& l) {
    h = __float2bfloat16_rn(x);
    l = __float2bfloat16_rn(x - __bfloat162float(h));
}
__device__ __forceinline__ void ldm_x4(uint32_t& r0, uint32_t& r1, uint32_t& r2, uint32_t& r3,
                                       uint32_t addr) {
    asm volatile("ldmatrix.sync.aligned.m8n8.x4.shared.b16 {%0,%1,%2,%3}, [%4];"
                 : "=r"(r0), "=r"(r1), "=r"(r2), "=r"(r3) : "r"(addr));
}
__device__ __forceinline__ void ldm_x4_t(uint32_t& r0, uint32_t& r1, uint32_t& r2, uint32_t& r3,
                                         uint32_t addr) {
    asm volatile("ldmatrix.sync.aligned.m8n8.x4.trans.shared.b16 {%0,%1,%2,%3}, [%4];"
                 : "=r"(r0), "=r"(r1), "=r"(r2), "=r"(r3) : "r"(addr));
}
__device__ __forceinline__ void mma16816(float* d, const uint32_t* a, uint32_t b0, uint32_t b1) {
    asm volatile(
        "mma.sync.aligned.m16n8k16.row.col.f32.bf16.bf16.f32 "
        "{%0,%1,%2,%3}, {%4,%5,%6,%7}, {%8,%9}, {%0,%1,%2,%3};"
        : "+f"(d[0]), "+f"(d[1]), "+f"(d[2]), "+f"(d[3])
        : "r"(a[0]), "r"(a[1]), "r"(a[2]), "r"(a[3]), "r"(b0), "r"(b1));
}

// ---------------------------------------------------------------------------
// conv_act: fp32 [M,1024] -> bf16 [M,3072] as [hi | hi | lo]
// ---------------------------------------------------------------------------
__global__ void conv_act(const float* __restrict__ X, __nv_bfloat16* __restrict__ Y)
{
    int idx = blockIdx.x * blockDim.x + threadIdx.x;
    int m  = idx >> 8;
    int c  = (idx & 255) * 4;
    float4 v = *reinterpret_cast<const float4*>(X + m * AD + c);
    __nv_bfloat16 h0,h1,h2,h3,l0,l1,l2,l3;
    split_hl(v.x, h0, l0); split_hl(v.y, h1, l1);
    split_hl(v.z, h2, l2); split_hl(v.w, h3, l3);
    uint2 hp = make_uint2(pack_bf16x2(h0,h1), pack_bf16x2(h2,h3));
    uint2 lp = make_uint2(pack_bf16x2(l0,l1), pack_bf16x2(l2,l3));
    size_t base = (size_t)m * KX + c;
    *reinterpret_cast<uint2*>(Y + base)        = hp;
    *reinterpret_cast<uint2*>(Y + base + 1024) = hp;
    *reinterpret_cast<uint2*>(Y + base + 2048) = lp;
}

// ---------------------------------------------------------------------------
// conv_wt: W[K][N] fp32 -> Wt[N][K'=3072] bf16 as [hi | lo | hi]
// ---------------------------------------------------------------------------
__global__ void conv_wt(const float* __restrict__ W, __nv_bfloat16* __restrict__ Wt)
{
    __shared__ float s[32][33];
    int n0 = blockIdx.x * 32;
    int k0 = blockIdx.y * 32;
    int tx = threadIdx.x, ty = threadIdx.y;
#pragma unroll
    for (int i = 0; i < 4; ++i)
        s[ty + 8 * i][tx] = W[(k0 + ty + 8 * i) * AD + n0 + tx];
    __syncthreads();
#pragma unroll
    for (int i = 0; i < 4; ++i) {
        int n = n0 + ty + 8 * i;
        int k = k0 + tx;
        float x = s[tx][ty + 8 * i];
        __nv_bfloat16 h, l;
        split_hl(x, h, l);
        size_t base = (size_t)n * KX + k;
        Wt[base]        = h;
        Wt[base + 1024] = l;
        Wt[base + 2048] = h;
    }
}

// ---------------------------------------------------------------------------
// bf16 mma GEMM, CTA 128x128, K chunks 64, cp.async double buffer.
// Epilogue: mode A (outH==null): fp32 C = acc + bias.
//           mode B: bf16 hi/lo head-planes, value = (acc + bias) * oscale.
// ---------------------------------------------------------------------------
#define GK_NC 48
#define SA0   0
#define SA1   16384
#define SB0   32768
#define SB1   49152
#define G_SMEM 65536

__device__ __forceinline__ void load_tile_cp(uint32_t sbase, uint32_t soff,
                                             const __nv_bfloat16* __restrict__ g,
                                             int row0, int kc, int tid)
{
#pragma unroll
    for (int i = 0; i < 4; ++i) {
        int idx = i * 256 + tid;
        int r = idx >> 3, seg = idx & 7;
        const char* src = (const char*)g + ((size_t)(row0 + r) * KX + kc) * 2 + seg * 16;
        uint32_t dst = sbase + soff + r * 128 + ((seg * 16) ^ ((r & 7) * 16));
        asm volatile("cp.async.cg.shared.global [%0], [%1], 16;" :: "r"(dst), "l"(src));
    }
}

__global__ __launch_bounds__(256, 2)
void gemm_mma(const __nv_bfloat16* __restrict__ A,
              const __nv_bfloat16* __restrict__ Bt,
              const float* __restrict__ bias,
              float* __restrict__ C,
              __nv_bfloat16* __restrict__ outH,
              __nv_bfloat16* __restrict__ outL,
              float oscale)
{
    extern __shared__ char smem[];
    const uint32_t sbase = smem_u32(smem);
    const int tid  = threadIdx.x;
    const int warp = tid >> 5;
    const int lane = tid & 31;
    const int bn = blockIdx.x * 128;
    const int bm = blockIdx.y * 128;

    const int wm0 = (warp >> 2) * 64;
    const int wn0 = (warp & 3) * 32;

    float d[4][4][4];
#pragma unroll
    for (int im = 0; im < 4; ++im)
#pragma unroll
        for (int jt = 0; jt < 4; ++jt)
#pragma unroll
            for (int q = 0; q < 4; ++q) d[im][jt][q] = 0.f;

    uint32_t a_rb[4], a_sw[4];
#pragma unroll
    for (int im = 0; im < 4; ++im) {
        int row = wm0 + im * 16 + (lane & 15);
        a_rb[im] = row * 128;
        a_sw[im] = (row & 7) * 16;
    }
    const uint32_t a_kb = (lane >> 4) * 16;
    uint32_t b_rb[2], b_sw[2];
#pragma unroll
    for (int jn = 0; jn < 2; ++jn) {
        int row = wn0 + jn * 16 + (lane & 7) + ((lane >> 4) << 3);
        b_rb[jn] = row * 128;
        b_sw[jn] = (row & 7) * 16;
    }
    const uint32_t b_kb = ((lane >> 3) & 1) * 16;

    load_tile_cp(sbase, SA0, A,  bm, 0, tid);
    load_tile_cp(sbase, SB0, Bt, bn, 0, tid);
    CP_COMMIT();

    for (int i = 0; i < GK_NC; ++i) {
        const uint32_t aoff = (i & 1) ? SA1 : SA0;
        const uint32_t boff = (i & 1) ? SB1 : SB0;
        if (i + 1 < GK_NC) {
            load_tile_cp(sbase, (i & 1) ? SA0 : SA1, A,  bm, (i + 1) * 64, tid);
            load_tile_cp(sbase, (i & 1) ? SB0 : SB1, Bt, bn, (i + 1) * 64, tid);
            CP_COMMIT();
            CP_WAIT(1);
        } else {
            CP_WAIT(0);
        }
        __syncthreads();

#pragma unroll
        for (int ks = 0; ks < 4; ++ks) {
            const uint32_t kb = ks * 32;
            uint32_t af[4][4];
#pragma unroll
            for (int im = 0; im < 4; ++im)
                ldm_x4(af[im][0], af[im][1], af[im][2], af[im][3],
                       sbase + aoff + a_rb[im] + ((kb + a_kb) ^ a_sw[im]));
            uint32_t bf[4][2];
#pragma unroll
            for (int jn = 0; jn < 2; ++jn) {
                uint32_t r0, r1, r2, r3;
                ldm_x4(r0, r1, r2, r3,
                       sbase + boff + b_rb[jn] + ((kb + b_kb) ^ b_sw[jn]));
                bf[jn * 2][0] = r0; bf[jn * 2][1] = r1;
                bf[jn * 2 + 1][0] = r2; bf[jn * 2 + 1][1] = r3;
            }
#pragma unroll
            for (int im = 0; im < 4; ++im)
#pragma unroll
                for (int jt = 0; jt < 4; ++jt)
                    mma16816(d[im][jt], af[im], bf[jt][0], bf[jt][1]);
        }
        __syncthreads();
    }

    if (outH == nullptr) {
#pragma unroll
        for (int jt = 0; jt < 4; ++jt) {
            const int c0 = bn + wn0 + jt * 8 + 2 * (lane & 3);
            float2 bb = *reinterpret_cast<const float2*>(bias + c0);
#pragma unroll
            for (int im = 0; im < 4; ++im) {
                const int r0 = bm + wm0 + im * 16 + (lane >> 2);
                float2 o0 = make_float2(d[im][jt][0] + bb.x, d[im][jt][1] + bb.y);
                float2 o1 = make_float2(d[im][jt][2] + bb.x, d[im][jt][3] + bb.y);
                *reinterpret_cast<float2*>(C + (size_t)r0 * AD + c0)       = o0;
                *reinterpret_cast<float2*>(C + (size_t)(r0 + 8) * AD + c0) = o1;
            }
        }
    } else {
        // head-plane bf16 hi/lo epilogue
#pragma unroll
        for (int jt = 0; jt < 4; ++jt) {
            const int c0 = bn + wn0 + jt * 8 + 2 * (lane & 3);
            float2 bb = *reinterpret_cast<const float2*>(bias + c0);
            const int hh = c0 >> 6, dd = c0 & 63;
#pragma unroll
            for (int im = 0; im < 4; ++im) {
                const int r0 = bm + wm0 + im * 16 + (lane >> 2);
#pragma unroll
                for (int half = 0; half < 2; ++half) {
                    const int r = r0 + half * 8;
                    float v0 = (d[im][jt][half * 2 + 0] + bb.x) * oscale;
                    float v1 = (d[im][jt][half * 2 + 1] + bb.y) * oscale;
                    __nv_bfloat16 h0, l0, h1, l1;
                    split_hl(v0, h0, l0); split_hl(v1, h1, l1);
                    size_t addr = ((size_t)((r >> 11) * NH + hh) * LL + (r & 2047)) * HD + dd;
                    *reinterpret_cast<uint32_t*>(outH + addr) = pack_bf16x2(h0, h1);
                    *reinterpret_cast<uint32_t*>(outL + addr) = pack_bf16x2(l0, l1);
                }
            }
        }
    }
}

// ---------------------------------------------------------------------------
// mma.sync flash attention.
// CTA = 128 q-rows x (one head, one batch); 8 warps, warp owns 16 full S rows.
// S = Qh Kh^T + Qh Kl^T + Ql Kh^T (fp32 acc, scale prefolded into Q planes).
// P fragments built in registers from S accumulators (acc layout == A layout).
// O += Ph Vh + Ph Vl + Pl Vh ; V B-fragments via ldmatrix.x4.trans.
// Double-buffered cp.async K/V chunks of 128 kv rows.
// ---------------------------------------------------------------------------
#define AT_QH 0
#define AT_QL 16384
#define AT_BUF 32768        // + buf*65536 + plane*16384 (KH,KL,VH,VL)
#define AT_SMEM (32768 + 2*65536)   // 163840

__device__ __forceinline__ void at_load_plane(uint32_t sb, uint32_t soff,
                                              const __nv_bfloat16* __restrict__ g,
                                              size_t pbase, int row0, int tid)
{
#pragma unroll
    for (int i = 0; i < 4; ++i) {
        int idx = i * 256 + tid;
        int r = idx >> 3, seg = idx & 7;
        const char* src = (const char*)(g + pbase + (size_t)(row0 + r) * HD) + seg * 16;
        uint32_t dst = sb + soff + r * 128 + ((seg * 16) ^ ((r & 7) * 16));
        asm volatile("cp.async.cg.shared.global [%0], [%1], 16;" :: "r"(dst), "l"(src));
    }
}

__global__ __launch_bounds__(256, 1)
void attn_mma(const __nv_bfloat16* __restrict__ Qh, const __nv_bfloat16* __restrict__ Ql,
              const __nv_bfloat16* __restrict__ Kh, const __nv_bfloat16* __restrict__ Kl,
              const __nv_bfloat16* __restrict__ Vh, const __nv_bfloat16* __restrict__ Vl,
              __nv_bfloat16* __restrict__ Oatt)
{
    extern __shared__ char smem[];
    const uint32_t sb = smem_u32(smem);
    const int tid  = threadIdx.x;
    const int warp = tid >> 5;
    const int lane = tid & 31;
    const int gidr = lane >> 2;          // accumulator row within 8
    const int tg   = lane & 3;

    const int qt = blockIdx.x, h = blockIdx.y, b = blockIdx.z;
    const size_t pbase = (size_t)(b * NH + h) * LL * HD;
    const int q0 = qt * 128;

    // prologue: Q (group), chunk0 (group), chunk1 (group)
    at_load_plane(sb, AT_QH, Qh, pbase, q0, tid);
    at_load_plane(sb, AT_QL, Ql, pbase, q0, tid);
    CP_COMMIT();
    {
        uint32_t bb0 = AT_BUF;
        at_load_plane(sb, bb0,         Kh, pbase, 0, tid);
        at_load_plane(sb, bb0 + 16384, Kl, pbase, 0, tid);
        at_load_plane(sb, bb0 + 32768, Vh, pbase, 0, tid);
        at_load_plane(sb, bb0 + 49152, Vl, pbase, 0, tid);
        CP_COMMIT();
        uint32_t bb1 = AT_BUF + 65536;
        at_load_plane(sb, bb1,         Kh, pbase, 128, tid);
        at_load_plane(sb, bb1 + 16384, Kl, pbase, 128, tid);
        at_load_plane(sb, bb1 + 32768, Vh, pbase, 128, tid);
        at_load_plane(sb, bb1 + 49152, Vl, pbase, 128, tid);
        CP_COMMIT();
    }

    // fragment address precompute
    const uint32_t a_row = 16 * warp + (lane & 15);
    const uint32_t a_off = a_row * 128;
    const uint32_t a_sw  = (a_row & 7) * 16;
    const uint32_t a_kb  = (lane >> 4) * 16;
    const uint32_t b_rowb = (lane & 7) + ((lane >> 4) << 3);
    const uint32_t b_kb   = ((lane >> 3) & 1) * 16;
    const uint32_t v_rowb = (lane & 15);
    const uint32_t v_cb   = (lane >> 4) * 16;

    float m0 = -1e30f, m1 = -1e30f, l0 = 0.f, l1 = 0.f;
    float O[8][4];
#pragma unroll
    for (int j = 0; j < 8; ++j)
#pragma unroll
        for (int q = 0; q < 4; ++q) O[j][q] = 0.f;

    for (int ci = 0; ci < 16; ++ci) {
        if (ci < 15) { CP_WAIT(1); } else { CP_WAIT(0); }
        __syncthreads();

        const uint32_t kh_ = sb + AT_BUF + (ci & 1) * 65536;
        const uint32_t kl_ = kh_ + 16384;
        const uint32_t vh_ = kh_ + 32768;
        const uint32_t vl_ = kh_ + 49152;

        // ---- S = QK^T, 3 split passes ----
        float s[16][4];
#pragma unroll
        for (int j = 0; j < 16; ++j)
#pragma unroll
            for (int q = 0; q < 4; ++q) s[j][q] = 0.f;

#pragma unroll
        for (int p = 0; p < 3; ++p) {
            const uint32_t ab = sb + (p < 2 ? AT_QH : AT_QL);
            const uint32_t bb_ = (p == 1) ? kl_ : kh_;
#pragma unroll
            for (int ks = 0; ks < 4; ++ks) {
                const uint32_t kb = ks * 32;
                uint32_t af[4];
                ldm_x4(af[0], af[1], af[2], af[3], ab + a_off + ((kb + a_kb) ^ a_sw));
#pragma unroll
                for (int jj = 0; jj < 8; ++jj) {
                    uint32_t row = 16 * jj + b_rowb;
                    uint32_t r0, r1, r2, r3;
                    ldm_x4(r0, r1, r2, r3, bb_ + row * 128 + ((kb + b_kb) ^ ((row & 7) * 16)));
                    mma16816(s[2 * jj],     af, r0, r1);
                    mma16816(s[2 * jj + 1], af, r2, r3);
                }
            }
        }

        // ---- online softmax prep (warp-local; quad covers all 128 cols) ----
        float cm0 = -1e30f, cm1 = -1e30f;
#pragma unroll
        for (int j = 0; j < 16; ++j) {
            cm0 = fmaxf(cm0, fmaxf(s[j][0], s[j][1]));
            cm1 = fmaxf(cm1, fmaxf(s[j][2], s[j][3]));
        }
        cm0 = fmaxf(cm0, __shfl_xor_sync(0xffffffffu, cm0, 1));
        cm0 = fmaxf(cm0, __shfl_xor_sync(0xffffffffu, cm0, 2));
        cm1 = fmaxf(cm1, __shfl_xor_sync(0xffffffffu, cm1, 1));
        cm1 = fmaxf(cm1, __shfl_xor_sync(0xffffffffu, cm1, 2));
        const float mn0 = fmaxf(m0, cm0);
        const float mn1 = fmaxf(m1, cm1);
        const float corr0 = __expf(m0 - mn0);
        const float corr1 = __expf(m1 - mn1);
        m0 = mn0; m1 = mn1;
#pragma unroll
        for (int j = 0; j < 8; ++j) {
            O[j][0] *= corr0; O[j][1] *= corr0;
            O[j][2] *= corr1; O[j][3] *= corr1;
        }
        l0 *= corr0; l1 *= corr1;

        float rs0 = 0.f, rs1 = 0.f;

        // ---- PV: convert P lazily per k-step, V frags via ldmatrix.trans ----
#pragma unroll
        for (int kk = 0; kk < 8; ++kk) {
            float p00 = __expf(s[2*kk][0]   - mn0);
            float p01 = __expf(s[2*kk][1]   - mn0);
            float p02 = __expf(s[2*kk][2]   - mn1);
            float p03 = __expf(s[2*kk][3]   - mn1);
            float p10 = __expf(s[2*kk+1][0] - mn0);
            float p11 = __expf(s[2*kk+1][1] - mn0);
            float p12 = __expf(s[2*kk+1][2] - mn1);
            float p13 = __expf(s[2*kk+1][3] - mn1);
            rs0 += (p00 + p01) + (p10 + p11);
            rs1 += (p02 + p03) + (p12 + p13);

            __nv_bfloat16 hh, ll;
            uint32_t ah[4], al[4];
            __nv_bfloat16 h00,l00,h01,l01,h02,l02,h03,l03;
            __nv_bfloat16 h10,l10,h11,l11,h12,l12,h13,l13;
            split_hl(p00,h00,l00); split_hl(p01,h01,l01);
            split_hl(p02,h02,l02); split_hl(p03,h03,l03);
            split_hl(p10,h10,l10); split_hl(p11,h11,l11);
            split_hl(p12,h12,l12); split_hl(p13,h13,l13);
            (void)hh; (void)ll;
            ah[0] = pack_bf16x2(h00,h01); ah[1] = pack_bf16x2(h02,h03);
            ah[2] = pack_bf16x2(h10,h11); ah[3] = pack_bf16x2(h12,h13);
            al[0] = pack_bf16x2(l00,l01); al[1] = pack_bf16x2(l02,l03);
            al[2] = pack_bf16x2(l10,l11); al[3] = pack_bf16x2(l12,l13);

            const uint32_t vrow = 16 * kk + v_rowb;
            const uint32_t vsw  = (vrow & 7) * 16;
            uint32_t vhf[8][2], vlf[8][2];
#pragma unroll
            for (int nb = 0; nb < 4; ++nb) {
                const uint32_t col = (nb * 32 + v_cb) ^ vsw;
                uint32_t r0, r1, r2, r3;
                ldm_x4_t(r0, r1, r2, r3, vh_ + vrow * 128 + col);
                vhf[2*nb][0] = r0; vhf[2*nb][1] = r1;
                vhf[2*nb+1][0] = r2; vhf[2*nb+1][1] = r3;
                ldm_x4_t(r0, r1, r2, r3, vl_ + vrow * 128 + col);
                vlf[2*nb][0] = r0; vlf[2*nb][1] = r1;
                vlf[2*nb+1][0] = r2; vlf[2*nb+1][1] = r3;
            }
#pragma unroll
            for (int jf = 0; jf < 8; ++jf) {
                mma16816(O[jf], ah, vhf[jf][0], vhf[jf][1]);
                mma16816(O[jf], ah, vlf[jf][0], vlf[jf][1]);
                mma16816(O[jf], al, vhf[jf][0], vhf[jf][1]);
            }
        }

        rs0 += __shfl_xor_sync(0xffffffffu, rs0, 1);
        rs0 += __shfl_xor_sync(0xffffffffu, rs0, 2);
        rs1 += __shfl_xor_sync(0xffffffffu, rs1, 1);
        rs1 += __shfl_xor_sync(0xffffffffu, rs1, 2);
        l0 += rs0; l1 += rs1;

        __syncthreads();   // everyone done reading buf (ci&1)
        if (ci + 2 < 16) {
            uint32_t bb = AT_BUF + (ci & 1) * 65536;
            int row0 = (ci + 2) * 128;
            at_load_plane(sb, bb,         Kh, pbase, row0, tid);
            at_load_plane(sb, bb + 16384, Kl, pbase, row0, tid);
            at_load_plane(sb, bb + 32768, Vh, pbase, row0, tid);
            at_load_plane(sb, bb + 49152, Vl, pbase, row0, tid);
            CP_COMMIT();
        }
    }

    // ---- epilogue: normalize, write bf16 hi|hi|lo into g_hl [M][3072] ----
    const float inv0 = 1.f / l0;
    const float inv1 = 1.f / l1;
    const int colb = h * HD + 2 * tg;
#pragma unroll
    for (int jf = 0; jf < 8; ++jf) {
#pragma unroll
        for (int half = 0; half < 2; ++half) {
            const int r = 16 * warp + gidr + half * 8;
            const float inv = half ? inv1 : inv0;
            float v0 = O[jf][half * 2 + 0] * inv;
            float v1 = O[jf][half * 2 + 1] * inv;
            __nv_bfloat16 h0, lo0, h1, lo1;
            split_hl(v0, h0, lo0); split_hl(v1, h1, lo1);
            uint32_t hp = pack_bf16x2(h0, h1);
            uint32_t lp = pack_bf16x2(lo0, lo1);
            size_t addr = (size_t)(b * LL + q0 + r) * KX + colb + 8 * jf;
            *reinterpret_cast<uint32_t*>(Oatt + addr)        = hp;
            *reinterpret_cast<uint32_t*>(Oatt + addr + 1024) = hp;
            *reinterpret_cast<uint32_t*>(Oatt + addr + 2048) = lp;
        }
    }
}

// ---------------------------------------------------------------------------
// Launch
// ---------------------------------------------------------------------------
extern "C" void kernel_launch(void* const* d_in, const int* in_sizes, int n_in,
                              void* d_out, int out_size)
{
    const float* query = (const float*)d_in[0];
    const float* key   = (const float*)d_in[1];
    const float* value = (const float*)d_in[2];
    const float* Wq = (const float*)d_in[3];
    const float* bq = (const float*)d_in[4];
    const float* Wk = (const float*)d_in[5];
    const float* bk = (const float*)d_in[6];
    const float* Wv = (const float*)d_in[7];
    const float* bv = (const float*)d_in[8];
    const float* Wo = (const float*)d_in[9];
    const float* bo = (const float*)d_in[10];
    float* out = (float*)d_out;

    __nv_bfloat16 *phl, *pwt, *qh, *ql, *kh, *kl, *vh, *vl;
    cudaGetSymbolAddress((void**)&phl, g_hl);
    cudaGetSymbolAddress((void**)&pwt, g_wt);
    cudaGetSymbolAddress((void**)&qh,  g_qh);
    cudaGetSymbolAddress((void**)&ql,  g_ql);
    cudaGetSymbolAddress((void**)&kh,  g_kh);
    cudaGetSymbolAddress((void**)&kl,  g_kl);
    cudaGetSymbolAddress((void**)&vh,  g_vh);
    cudaGetSymbolAddress((void**)&vl,  g_vl);

    cudaFuncSetAttribute(gemm_mma, cudaFuncAttributeMaxDynamicSharedMemorySize, G_SMEM);
    cudaFuncSetAttribute(attn_mma, cudaFuncAttributeMaxDynamicSharedMemorySize, AT_SMEM);

    __nv_bfloat16* wtq = pwt + 0 * (size_t)(AD * KX);
    __nv_bfloat16* wtk = pwt + 1 * (size_t)(AD * KX);
    __nv_bfloat16* wtv = pwt + 2 * (size_t)(AD * KX);
    __nv_bfloat16* wto = pwt + 3 * (size_t)(AD * KX);

    dim3 wgrid(32, 32), wblk(32, 8);
    conv_wt<<<wgrid, wblk>>>(Wq, wtq);
    conv_wt<<<wgrid, wblk>>>(Wk, wtk);
    conv_wt<<<wgrid, wblk>>>(Wv, wtv);
    conv_wt<<<wgrid, wblk>>>(Wo, wto);

    dim3 ggrid(AD / 128, MM / 128);   // (8, 64)

    conv_act<<<MM, 256>>>(query, phl);
    gemm_mma<<<ggrid, 256, G_SMEM>>>(phl, wtq, bq, nullptr, qh, ql, 0.125f);

    conv_act<<<MM, 256>>>(key, phl);
    gemm_mma<<<ggrid, 256, G_SMEM>>>(phl, wtk, bk, nullptr, kh, kl, 1.0f);

    conv_act<<<MM, 256>>>(value, phl);
    gemm_mma<<<ggrid, 256, G_SMEM>>>(phl, wtv, bv, nullptr, vh, vl, 1.0f);

    dim3 agrid(LL / 128, NH, BB);     // (16, 16, 4)
    attn_mma<<<agrid, 256, AT_SMEM>>>(qh, ql, kh, kl, vh, vl, phl);

    gemm_mma<<<ggrid, 256, G_SMEM>>>(phl, wto, bo, out, nullptr, nullptr, 1.0f);
}

// round 8
// speedup vs baseline: 6.8176x; 2.5433x over previous
#include <cuda_runtime.h>
#include <cuda_fp16.h>
#include <cstdint>

// Problem constants
#define BB   4
#define LL   2048
#define AD   1024
#define NH   16
#define HD   64
#define MM   (BB*LL)   // 8192

// ---------------------------------------------------------------------------
// Scratch (device globals)
// ---------------------------------------------------------------------------
__device__ __half g_act[MM * AD];        // fp16 activations (GEMM A, reused)
__device__ __half g_wt [4][AD * AD];     // weights^T fp16
__device__ __half g_qh [MM * AD];        // head-plane Q (prescaled by 0.125)
__device__ __half g_kh [MM * AD];        // head-plane K
__device__ __half g_vh [MM * AD];        // head-plane V
__device__ __half g_ao [MM * AD];        // attention output fp16 [M,1024]

// ---------------------------------------------------------------------------
// Helpers (plain sm_103-legal: cp.async, ldmatrix, mma.sync)
// ---------------------------------------------------------------------------
__device__ __forceinline__ uint32_t smem_u32(const void* p) {
    uint32_t a;
    asm("{ .reg .u64 t; cvta.to.shared.u64 t, %1; cvt.u32.u64 %0, t; }" : "=r"(a) : "l"(p));
    return a;
}
#define CP_COMMIT()  asm volatile("cp.async.commit_group;" ::: "memory")
#define CP_WAIT(n)   asm volatile("cp.async.wait_group %0;" :: "n"(n) : "memory")

__device__ __forceinline__ uint32_t pack_h2(__half a, __half b) {
    return (uint32_t)__half_as_ushort(a) | ((uint32_t)__half_as_ushort(b) << 16);
}
__device__ __forceinline__ void ldm_x4(uint32_t& r0, uint32_t& r1, uint32_t& r2, uint32_t& r3,
                                       uint32_t addr) {
    asm volatile("ldmatrix.sync.aligned.m8n8.x4.shared.b16 {%0,%1,%2,%3}, [%4];"
                 : "=r"(r0), "=r"(r1), "=r"(r2), "=r"(r3) : "r"(addr));
}
__device__ __forceinline__ void ldm_x4_t(uint32_t& r0, uint32_t& r1, uint32_t& r2, uint32_t& r3,
                                         uint32_t addr) {
    asm volatile("ldmatrix.sync.aligned.m8n8.x4.trans.shared.b16 {%0,%1,%2,%3}, [%4];"
                 : "=r"(r0), "=r"(r1), "=r"(r2), "=r"(r3) : "r"(addr));
}
__device__ __forceinline__ void mma16816(float* d, const uint32_t* a, uint32_t b0, uint32_t b1) {
    asm volatile(
        "mma.sync.aligned.m16n8k16.row.col.f32.f16.f16.f32 "
        "{%0,%1,%2,%3}, {%4,%5,%6,%7}, {%8,%9}, {%0,%1,%2,%3};"
        : "+f"(d[0]), "+f"(d[1]), "+f"(d[2]), "+f"(d[3])
        : "r"(a[0]), "r"(a[1]), "r"(a[2]), "r"(a[3]), "r"(b0), "r"(b1));
}

// ---------------------------------------------------------------------------
// conv_act: fp32 [M,1024] -> fp16 [M,1024]
// ---------------------------------------------------------------------------
__global__ void conv_act(const float* __restrict__ X, __half* __restrict__ Y)
{
    int idx = blockIdx.x * blockDim.x + threadIdx.x;
    int m = idx >> 8;
    int c = (idx & 255) * 4;
    float4 v = *reinterpret_cast<const float4*>(X + m * AD + c);
    uint2 o;
    o.x = pack_h2(__float2half_rn(v.x), __float2half_rn(v.y));
    o.y = pack_h2(__float2half_rn(v.z), __float2half_rn(v.w));
    *reinterpret_cast<uint2*>(Y + (size_t)m * AD + c) = o;
}

// ---------------------------------------------------------------------------
// conv_wt: W[K=1024][N=1024] fp32 -> Wt[N][K] fp16 (transpose)
// ---------------------------------------------------------------------------
__global__ void conv_wt(const float* __restrict__ W, __half* __restrict__ Wt)
{
    __shared__ float s[32][33];
    int n0 = blockIdx.x * 32;
    int k0 = blockIdx.y * 32;
    int tx = threadIdx.x, ty = threadIdx.y;   // (32, 8)
#pragma unroll
    for (int i = 0; i < 4; ++i)
        s[ty + 8 * i][tx] = W[(k0 + ty + 8 * i) * AD + n0 + tx];
    __syncthreads();
#pragma unroll
    for (int i = 0; i < 4; ++i) {
        int n = n0 + ty + 8 * i;
        int k = k0 + tx;
        Wt[(size_t)n * AD + k] = __float2half_rn(s[tx][ty + 8 * i]);
    }
}

// ---------------------------------------------------------------------------
// fp16 mma GEMM: C[M,1024] = A[M,1024] x Wt[1024,1024]^T + bias
// CTA 128x128, K chunks 64, cp.async double buffer, swizzled 128B smem rows.
// Epilogue: outH==null -> fp32 C;  else fp16 head-plane, (acc+bias)*oscale.
// ---------------------------------------------------------------------------
#define GK_NC 16
#define SA0   0
#define SA1   16384
#define SB0   32768
#define SB1   49152
#define G_SMEM 65536

__device__ __forceinline__ void load_tile_cp(uint32_t sbase, uint32_t soff,
                                             const __half* __restrict__ g,
                                             int row0, int kc, int tid)
{
#pragma unroll
    for (int i = 0; i < 4; ++i) {
        int idx = i * 256 + tid;
        int r = idx >> 3, seg = idx & 7;
        const char* src = (const char*)g + ((size_t)(row0 + r) * AD + kc) * 2 + seg * 16;
        uint32_t dst = sbase + soff + r * 128 + ((seg * 16) ^ ((r & 7) * 16));
        asm volatile("cp.async.cg.shared.global [%0], [%1], 16;" :: "r"(dst), "l"(src));
    }
}

__global__ __launch_bounds__(256, 2)
void gemm_mma(const __half* __restrict__ A,
              const __half* __restrict__ Bt,
              const float* __restrict__ bias,
              float* __restrict__ C,
              __half* __restrict__ outH,
              float oscale)
{
    extern __shared__ char smem[];
    const uint32_t sbase = smem_u32(smem);
    const int tid  = threadIdx.x;
    const int warp = tid >> 5;
    const int lane = tid & 31;
    const int bn = blockIdx.x * 128;
    const int bm = blockIdx.y * 128;

    const int wm0 = (warp >> 2) * 64;
    const int wn0 = (warp & 3) * 32;

    float d[4][4][4];
#pragma unroll
    for (int im = 0; im < 4; ++im)
#pragma unroll
        for (int jt = 0; jt < 4; ++jt)
#pragma unroll
            for (int q = 0; q < 4; ++q) d[im][jt][q] = 0.f;

    uint32_t a_rb[4], a_sw[4];
#pragma unroll
    for (int im = 0; im < 4; ++im) {
        int row = wm0 + im * 16 + (lane & 15);
        a_rb[im] = row * 128;
        a_sw[im] = (row & 7) * 16;
    }
    const uint32_t a_kb = (lane >> 4) * 16;
    uint32_t b_rb[2], b_sw[2];
#pragma unroll
    for (int jn = 0; jn < 2; ++jn) {
        int row = wn0 + jn * 16 + (lane & 7) + ((lane >> 4) << 3);
        b_rb[jn] = row * 128;
        b_sw[jn] = (row & 7) * 16;
    }
    const uint32_t b_kb = ((lane >> 3) & 1) * 16;

    load_tile_cp(sbase, SA0, A,  bm, 0, tid);
    load_tile_cp(sbase, SB0, Bt, bn, 0, tid);
    CP_COMMIT();

    for (int i = 0; i < GK_NC; ++i) {
        const uint32_t aoff = (i & 1) ? SA1 : SA0;
        const uint32_t boff = (i & 1) ? SB1 : SB0;
        if (i + 1 < GK_NC) {
            load_tile_cp(sbase, (i & 1) ? SA0 : SA1, A,  bm, (i + 1) * 64, tid);
            load_tile_cp(sbase, (i & 1) ? SB0 : SB1, Bt, bn, (i + 1) * 64, tid);
            CP_COMMIT();
            CP_WAIT(1);
        } else {
            CP_WAIT(0);
        }
        __syncthreads();

#pragma unroll
        for (int ks = 0; ks < 4; ++ks) {
            const uint32_t kb = ks * 32;
            uint32_t af[4][4];
#pragma unroll
            for (int im = 0; im < 4; ++im)
                ldm_x4(af[im][0], af[im][1], af[im][2], af[im][3],
                       sbase + aoff + a_rb[im] + ((kb + a_kb) ^ a_sw[im]));
            uint32_t bf[4][2];
#pragma unroll
            for (int jn = 0; jn < 2; ++jn) {
                uint32_t r0, r1, r2, r3;
                ldm_x4(r0, r1, r2, r3,
                       sbase + boff + b_rb[jn] + ((kb + b_kb) ^ b_sw[jn]));
                bf[jn * 2][0] = r0; bf[jn * 2][1] = r1;
                bf[jn * 2 + 1][0] = r2; bf[jn * 2 + 1][1] = r3;
            }
#pragma unroll
            for (int im = 0; im < 4; ++im)
#pragma unroll
                for (int jt = 0; jt < 4; ++jt)
                    mma16816(d[im][jt], af[im], bf[jt][0], bf[jt][1]);
        }
        __syncthreads();
    }

    if (outH == nullptr) {
#pragma unroll
        for (int jt = 0; jt < 4; ++jt) {
            const int c0 = bn + wn0 + jt * 8 + 2 * (lane & 3);
            float2 bb = *reinterpret_cast<const float2*>(bias + c0);
#pragma unroll
            for (int im = 0; im < 4; ++im) {
                const int r0 = bm + wm0 + im * 16 + (lane >> 2);
                float2 o0 = make_float2(d[im][jt][0] + bb.x, d[im][jt][1] + bb.y);
                float2 o1 = make_float2(d[im][jt][2] + bb.x, d[im][jt][3] + bb.y);
                *reinterpret_cast<float2*>(C + (size_t)r0 * AD + c0)       = o0;
                *reinterpret_cast<float2*>(C + (size_t)(r0 + 8) * AD + c0) = o1;
            }
        }
    } else {
        // fp16 head-plane epilogue: [(b*NH+h)][L][64]
#pragma unroll
        for (int jt = 0; jt < 4; ++jt) {
            const int c0 = bn + wn0 + jt * 8 + 2 * (lane & 3);
            float2 bb = *reinterpret_cast<const float2*>(bias + c0);
            const int hh = c0 >> 6, dd = c0 & 63;
#pragma unroll
            for (int im = 0; im < 4; ++im) {
                const int r0 = bm + wm0 + im * 16 + (lane >> 2);
#pragma unroll
                for (int half = 0; half < 2; ++half) {
                    const int r = r0 + half * 8;
                    float v0 = (d[im][jt][half * 2 + 0] + bb.x) * oscale;
                    float v1 = (d[im][jt][half * 2 + 1] + bb.y) * oscale;
                    size_t addr = ((size_t)((r >> 11) * NH + hh) * LL + (r & 2047)) * HD + dd;
                    *reinterpret_cast<uint32_t*>(outH + addr) =
                        pack_h2(__float2half_rn(v0), __float2half_rn(v1));
                }
            }
        }
    }
}

// ---------------------------------------------------------------------------
// fp16 mma flash attention.
// CTA = 64 q-rows x (head, batch); 128 threads / 4 warps; warp owns 16 rows.
// S = Qh Kh^T (1 pass, scale prefolded into Q). P rounded to fp16 in regs
// (accumulator layout == A-fragment layout). O += P Vh (1 mma per frag).
// KV chunks of 128 rows, double-buffered cp.async. 3 CTAs/SM.
// ---------------------------------------------------------------------------
#define AT_Q   0
#define AT_BUF 8192                     // + buf*32768 ; Kh at +0, Vh at +16384
#define AT_SMEM (8192 + 2*32768)        // 73728

__device__ __forceinline__ void at_load_plane(uint32_t sb, uint32_t soff,
                                              const __half* __restrict__ g,
                                              size_t pbase, int row0, int nrows, int tid)
{
    const int iters = nrows / 16;       // 128 threads, 8 segs/row
#pragma unroll
    for (int i = 0; i < 8; ++i) {
        if (i >= iters) break;
        int idx = i * 128 + tid;
        int r = idx >> 3, seg = idx & 7;
        const char* src = (const char*)(g + pbase + (size_t)(row0 + r) * HD) + seg * 16;
        uint32_t dst = sb + soff + r * 128 + ((seg * 16) ^ ((r & 7) * 16));
        asm volatile("cp.async.cg.shared.global [%0], [%1], 16;" :: "r"(dst), "l"(src));
    }
}

__global__ __launch_bounds__(128, 3)
void attn_mma(const __half* __restrict__ Qh,
              const __half* __restrict__ Kh,
              const __half* __restrict__ Vh,
              __half* __restrict__ Oatt)
{
    extern __shared__ char smem[];
    const uint32_t sb = smem_u32(smem);
    const int tid  = threadIdx.x;
    const int warp = tid >> 5;
    const int lane = tid & 31;
    const int gidr = lane >> 2;
    const int tg   = lane & 3;

    const int qt = blockIdx.x, h = blockIdx.y, b = blockIdx.z;
    const size_t pbase = (size_t)(b * NH + h) * LL * HD;
    const int q0 = qt * 64;

    // prologue
    at_load_plane(sb, AT_Q, Qh, pbase, q0, 64, tid);
    CP_COMMIT();
    at_load_plane(sb, AT_BUF,         Kh, pbase, 0, 128, tid);
    at_load_plane(sb, AT_BUF + 16384, Vh, pbase, 0, 128, tid);
    CP_COMMIT();
    at_load_plane(sb, AT_BUF + 32768, Kh, pbase, 128, 128, tid);
    at_load_plane(sb, AT_BUF + 49152, Vh, pbase, 128, 128, tid);
    CP_COMMIT();

    const uint32_t a_row = 16 * warp + (lane & 15);
    const uint32_t a_off = a_row * 128;
    const uint32_t a_sw  = (a_row & 7) * 16;
    const uint32_t a_kb  = (lane >> 4) * 16;
    const uint32_t b_rowb = (lane & 7) + ((lane >> 4) << 3);
    const uint32_t b_kb   = ((lane >> 3) & 1) * 16;
    const uint32_t v_rowb = (lane & 15);
    const uint32_t v_cb   = (lane >> 4) * 16;

    float m0 = -1e30f, m1 = -1e30f, l0 = 0.f, l1 = 0.f;
    float O[8][4];
#pragma unroll
    for (int j = 0; j < 8; ++j)
#pragma unroll
        for (int q = 0; q < 4; ++q) O[j][q] = 0.f;

    for (int ci = 0; ci < 16; ++ci) {
        if (ci < 15) { CP_WAIT(1); } else { CP_WAIT(0); }
        __syncthreads();

        const uint32_t kh_ = sb + AT_BUF + (ci & 1) * 32768;
        const uint32_t vh_ = kh_ + 16384;

        // ---- S = Q K^T (single fp16 pass) ----
        float s[16][4];
#pragma unroll
        for (int j = 0; j < 16; ++j)
#pragma unroll
            for (int q = 0; q < 4; ++q) s[j][q] = 0.f;

#pragma unroll
        for (int ks = 0; ks < 4; ++ks) {
            const uint32_t kb = ks * 32;
            uint32_t af[4];
            ldm_x4(af[0], af[1], af[2], af[3], sb + AT_Q + a_off + ((kb + a_kb) ^ a_sw));
#pragma unroll
            for (int jj = 0; jj < 8; ++jj) {
                uint32_t row = 16 * jj + b_rowb;
                uint32_t r0, r1, r2, r3;
                ldm_x4(r0, r1, r2, r3, kh_ + row * 128 + ((kb + b_kb) ^ ((row & 7) * 16)));
                mma16816(s[2 * jj],     af, r0, r1);
                mma16816(s[2 * jj + 1], af, r2, r3);
            }
        }

        // ---- online softmax (quad shuffles cover all 128 cols per row) ----
        float cm0 = -1e30f, cm1 = -1e30f;
#pragma unroll
        for (int j = 0; j < 16; ++j) {
            cm0 = fmaxf(cm0, fmaxf(s[j][0], s[j][1]));
            cm1 = fmaxf(cm1, fmaxf(s[j][2], s[j][3]));
        }
        cm0 = fmaxf(cm0, __shfl_xor_sync(0xffffffffu, cm0, 1));
        cm0 = fmaxf(cm0, __shfl_xor_sync(0xffffffffu, cm0, 2));
        cm1 = fmaxf(cm1, __shfl_xor_sync(0xffffffffu, cm1, 1));
        cm1 = fmaxf(cm1, __shfl_xor_sync(0xffffffffu, cm1, 2));
        const float mn0 = fmaxf(m0, cm0);
        const float mn1 = fmaxf(m1, cm1);
        const float corr0 = __expf(m0 - mn0);
        const float corr1 = __expf(m1 - mn1);
        m0 = mn0; m1 = mn1;
#pragma unroll
        for (int j = 0; j < 8; ++j) {
            O[j][0] *= corr0; O[j][1] *= corr0;
            O[j][2] *= corr1; O[j][3] *= corr1;
        }
        l0 *= corr0; l1 *= corr1;

        float rs0 = 0.f, rs1 = 0.f;

        // ---- PV: P fp16 in regs, V B-fragments via ldmatrix.trans ----
#pragma unroll
        for (int kk = 0; kk < 8; ++kk) {
            float p00 = __expf(s[2*kk][0]   - mn0);
            float p01 = __expf(s[2*kk][1]   - mn0);
            float p02 = __expf(s[2*kk][2]   - mn1);
            float p03 = __expf(s[2*kk][3]   - mn1);
            float p10 = __expf(s[2*kk+1][0] - mn0);
            float p11 = __expf(s[2*kk+1][1] - mn0);
            float p12 = __expf(s[2*kk+1][2] - mn1);
            float p13 = __expf(s[2*kk+1][3] - mn1);
            rs0 += (p00 + p01) + (p10 + p11);
            rs1 += (p02 + p03) + (p12 + p13);

            uint32_t ah[4];
            ah[0] = pack_h2(__float2half_rn(p00), __float2half_rn(p01));
            ah[1] = pack_h2(__float2half_rn(p02), __float2half_rn(p03));
            ah[2] = pack_h2(__float2half_rn(p10), __float2half_rn(p11));
            ah[3] = pack_h2(__float2half_rn(p12), __float2half_rn(p13));

            const uint32_t vrow = 16 * kk + v_rowb;
            const uint32_t vsw  = (vrow & 7) * 16;
            uint32_t vhf[8][2];
#pragma unroll
            for (int nb = 0; nb < 4; ++nb) {
                const uint32_t col = (nb * 32 + v_cb) ^ vsw;
                uint32_t r0, r1, r2, r3;
                ldm_x4_t(r0, r1, r2, r3, vh_ + vrow * 128 + col);
                vhf[2*nb][0] = r0;   vhf[2*nb][1] = r1;
                vhf[2*nb+1][0] = r2; vhf[2*nb+1][1] = r3;
            }
#pragma unroll
            for (int jf = 0; jf < 8; ++jf)
                mma16816(O[jf], ah, vhf[jf][0], vhf[jf][1]);
        }

        rs0 += __shfl_xor_sync(0xffffffffu, rs0, 1);
        rs0 += __shfl_xor_sync(0xffffffffu, rs0, 2);
        rs1 += __shfl_xor_sync(0xffffffffu, rs1, 1);
        rs1 += __shfl_xor_sync(0xffffffffu, rs1, 2);
        l0 += rs0; l1 += rs1;

        __syncthreads();   // all warps done reading buf (ci&1)
        if (ci + 2 < 16) {
            uint32_t bb = AT_BUF + (ci & 1) * 32768;
            int row0 = (ci + 2) * 128;
            at_load_plane(sb, bb,         Kh, pbase, row0, 128, tid);
            at_load_plane(sb, bb + 16384, Vh, pbase, row0, 128, tid);
            CP_COMMIT();
        }
    }

    // ---- epilogue: normalize, write fp16 into g_ao [M,1024] ----
    const float inv0 = 1.f / l0;
    const float inv1 = 1.f / l1;
    const int colb = h * HD + 2 * tg;
#pragma unroll
    for (int jf = 0; jf < 8; ++jf) {
#pragma unroll
        for (int half = 0; half < 2; ++half) {
            const int r = 16 * warp + gidr + half * 8;
            const float inv = half ? inv1 : inv0;
            float v0 = O[jf][half * 2 + 0] * inv;
            float v1 = O[jf][half * 2 + 1] * inv;
            size_t addr = (size_t)(b * LL + q0 + r) * AD + colb + 8 * jf;
            *reinterpret_cast<uint32_t*>(Oatt + addr) =
                pack_h2(__float2half_rn(v0), __float2half_rn(v1));
        }
    }
}

// ---------------------------------------------------------------------------
// Launch
// ---------------------------------------------------------------------------
extern "C" void kernel_launch(void* const* d_in, const int* in_sizes, int n_in,
                              void* d_out, int out_size)
{
    const float* query = (const float*)d_in[0];
    const float* key   = (const float*)d_in[1];
    const float* value = (const float*)d_in[2];
    const float* Wq = (const float*)d_in[3];
    const float* bq = (const float*)d_in[4];
    const float* Wk = (const float*)d_in[5];
    const float* bk = (const float*)d_in[6];
    const float* Wv = (const float*)d_in[7];
    const float* bv = (const float*)d_in[8];
    const float* Wo = (const float*)d_in[9];
    const float* bo = (const float*)d_in[10];
    float* out = (float*)d_out;

    __half *pact, *pwt, *qh, *kh, *vh, *pao;
    cudaGetSymbolAddress((void**)&pact, g_act);
    cudaGetSymbolAddress((void**)&pwt,  g_wt);
    cudaGetSymbolAddress((void**)&qh,   g_qh);
    cudaGetSymbolAddress((void**)&kh,   g_kh);
    cudaGetSymbolAddress((void**)&vh,   g_vh);
    cudaGetSymbolAddress((void**)&pao,  g_ao);

    cudaFuncSetAttribute(gemm_mma, cudaFuncAttributeMaxDynamicSharedMemorySize, G_SMEM);
    cudaFuncSetAttribute(attn_mma, cudaFuncAttributeMaxDynamicSharedMemorySize, AT_SMEM);

    __half* wtq = pwt + 0 * (size_t)(AD * AD);
    __half* wtk = pwt + 1 * (size_t)(AD * AD);
    __half* wtv = pwt + 2 * (size_t)(AD * AD);
    __half* wto = pwt + 3 * (size_t)(AD * AD);

    dim3 wgrid(32, 32), wblk(32, 8);
    conv_wt<<<wgrid, wblk>>>(Wq, wtq);
    conv_wt<<<wgrid, wblk>>>(Wk, wtk);
    conv_wt<<<wgrid, wblk>>>(Wv, wtv);
    conv_wt<<<wgrid, wblk>>>(Wo, wto);

    dim3 ggrid(AD / 128, MM / 128);   // (8, 64)

    conv_act<<<MM, 256>>>(query, pact);
    gemm_mma<<<ggrid, 256, G_SMEM>>>(pact, wtq, bq, nullptr, qh, 0.125f);

    conv_act<<<MM, 256>>>(key, pact);
    gemm_mma<<<ggrid, 256, G_SMEM>>>(pact, wtk, bk, nullptr, kh, 1.0f);

    conv_act<<<MM, 256>>>(value, pact);
    gemm_mma<<<ggrid, 256, G_SMEM>>>(pact, wtv, bv, nullptr, vh, 1.0f);

    dim3 agrid(LL / 64, NH, BB);      // (32, 16, 4)
    attn_mma<<<agrid, 128, AT_SMEM>>>(qh, kh, vh, pao);

    gemm_mma<<<ggrid, 256, G_SMEM>>>(pao, wto, bo, out, nullptr, 1.0f);
}

// round 9
// speedup vs baseline: 7.2074x; 1.0572x over previous
#include <cuda_runtime.h>
#include <cuda_fp16.h>
#include <cstdint>

// Problem constants
#define BB   4
#define LL   2048
#define AD   1024
#define NH   16
#define HD   64
#define MM   (BB*LL)   // 8192

// ---------------------------------------------------------------------------
// Scratch (device globals)
// ---------------------------------------------------------------------------
__device__ __half g_acts [3 * MM * AD];    // fp16 activations q|k|v
__device__ __half g_wt   [4 * AD * AD];    // weights^T fp16 (q,k,v,o)
__device__ __half g_heads[3 * MM * AD];    // head planes Q(prescaled)|K|V
__device__ __half g_ao   [MM * AD];        // attention output fp16 [M,1024]

// ---------------------------------------------------------------------------
// Helpers (plain sm_103-legal: cp.async, ldmatrix, mma.sync)
// ---------------------------------------------------------------------------
__device__ __forceinline__ uint32_t smem_u32(const void* p) {
    uint32_t a;
    asm("{ .reg .u64 t; cvta.to.shared.u64 t, %1; cvt.u32.u64 %0, t; }" : "=r"(a) : "l"(p));
    return a;
}
#define CP_COMMIT()  asm volatile("cp.async.commit_group;" ::: "memory")
#define CP_WAIT(n)   asm volatile("cp.async.wait_group %0;" :: "n"(n) : "memory")

__device__ __forceinline__ uint32_t pack_h2(__half a, __half b) {
    return (uint32_t)__half_as_ushort(a) | ((uint32_t)__half_as_ushort(b) << 16);
}
__device__ __forceinline__ void ldm_x4(uint32_t& r0, uint32_t& r1, uint32_t& r2, uint32_t& r3,
                                       uint32_t addr) {
    asm volatile("ldmatrix.sync.aligned.m8n8.x4.shared.b16 {%0,%1,%2,%3}, [%4];"
                 : "=r"(r0), "=r"(r1), "=r"(r2), "=r"(r3) : "r"(addr));
}
__device__ __forceinline__ void ldm_x4_t(uint32_t& r0, uint32_t& r1, uint32_t& r2, uint32_t& r3,
                                         uint32_t addr) {
    asm volatile("ldmatrix.sync.aligned.m8n8.x4.trans.shared.b16 {%0,%1,%2,%3}, [%4];"
                 : "=r"(r0), "=r"(r1), "=r"(r2), "=r"(r3) : "r"(addr));
}
__device__ __forceinline__ void mma16816(float* d, const uint32_t* a, uint32_t b0, uint32_t b1) {
    asm volatile(
        "mma.sync.aligned.m16n8k16.row.col.f32.f16.f16.f32 "
        "{%0,%1,%2,%3}, {%4,%5,%6,%7}, {%8,%9}, {%0,%1,%2,%3};"
        : "+f"(d[0]), "+f"(d[1]), "+f"(d[2]), "+f"(d[3])
        : "r"(a[0]), "r"(a[1]), "r"(a[2]), "r"(a[3]), "r"(b0), "r"(b1));
}

// ---------------------------------------------------------------------------
// conv_act fused: 3 inputs fp32 [M,1024] -> fp16, selected by blockIdx.y
// ---------------------------------------------------------------------------
__global__ void conv_act3(const float* __restrict__ X0, const float* __restrict__ X1,
                          const float* __restrict__ X2, __half* __restrict__ Y)
{
    const int z = blockIdx.y;
    const float* X = (z == 0) ? X0 : (z == 1) ? X1 : X2;
    int m = blockIdx.x;
    int c = threadIdx.x * 4;
    float4 v = *reinterpret_cast<const float4*>(X + (size_t)m * AD + c);
    uint2 o;
    o.x = pack_h2(__float2half_rn(v.x), __float2half_rn(v.y));
    o.y = pack_h2(__float2half_rn(v.z), __float2half_rn(v.w));
    *reinterpret_cast<uint2*>(Y + (size_t)z * MM * AD + (size_t)m * AD + c) = o;
}

// ---------------------------------------------------------------------------
// conv_wt fused: 4 weights W[K][N] fp32 -> Wt[N][K] fp16, selected by blockIdx.z
// ---------------------------------------------------------------------------
__global__ void conv_wt4(const float* __restrict__ W0, const float* __restrict__ W1,
                         const float* __restrict__ W2, const float* __restrict__ W3,
                         __half* __restrict__ WtBase)
{
    __shared__ float s[32][33];
    const int z = blockIdx.z;
    const float* W = (z == 0) ? W0 : (z == 1) ? W1 : (z == 2) ? W2 : W3;
    __half* Wt = WtBase + (size_t)z * AD * AD;
    int n0 = blockIdx.x * 32;
    int k0 = blockIdx.y * 32;
    int tx = threadIdx.x, ty = threadIdx.y;   // (32, 8)
#pragma unroll
    for (int i = 0; i < 4; ++i)
        s[ty + 8 * i][tx] = W[(size_t)(k0 + ty + 8 * i) * AD + n0 + tx];
    __syncthreads();
#pragma unroll
    for (int i = 0; i < 4; ++i) {
        int n = n0 + ty + 8 * i;
        int k = k0 + tx;
        Wt[(size_t)n * AD + k] = __float2half_rn(s[tx][ty + 8 * i]);
    }
}

// ---------------------------------------------------------------------------
// fp16 mma GEMM core (inlined into two wrappers below).
// CTA 128x128, K chunks 64, cp.async double buffer, swizzled 128B smem rows.
// ---------------------------------------------------------------------------
#define GK_NC 16
#define SA0   0
#define SA1   16384
#define SB0   32768
#define SB1   49152
#define G_SMEM 65536

__device__ __forceinline__ void load_tile_cp(uint32_t sbase, uint32_t soff,
                                             const __half* __restrict__ g,
                                             int row0, int kc, int tid)
{
#pragma unroll
    for (int i = 0; i < 4; ++i) {
        int idx = i * 256 + tid;
        int r = idx >> 3, seg = idx & 7;
        const char* src = (const char*)g + ((size_t)(row0 + r) * AD + kc) * 2 + seg * 16;
        uint32_t dst = sbase + soff + r * 128 + ((seg * 16) ^ ((r & 7) * 16));
        asm volatile("cp.async.cg.shared.global [%0], [%1], 16;" :: "r"(dst), "l"(src));
    }
}

__device__ __forceinline__ void gemm_body(const __half* __restrict__ A,
                                          const __half* __restrict__ Bt,
                                          const float* __restrict__ bias,
                                          float* __restrict__ C,
                                          __half* __restrict__ outH,
                                          float oscale,
                                          char* smem)
{
    const uint32_t sbase = smem_u32(smem);
    const int tid  = threadIdx.x;
    const int warp = tid >> 5;
    const int lane = tid & 31;
    const int bn = blockIdx.x * 128;
    const int bm = blockIdx.y * 128;

    const int wm0 = (warp >> 2) * 64;
    const int wn0 = (warp & 3) * 32;

    float d[4][4][4];
#pragma unroll
    for (int im = 0; im < 4; ++im)
#pragma unroll
        for (int jt = 0; jt < 4; ++jt)
#pragma unroll
            for (int q = 0; q < 4; ++q) d[im][jt][q] = 0.f;

    uint32_t a_rb[4], a_sw[4];
#pragma unroll
    for (int im = 0; im < 4; ++im) {
        int row = wm0 + im * 16 + (lane & 15);
        a_rb[im] = row * 128;
        a_sw[im] = (row & 7) * 16;
    }
    const uint32_t a_kb = (lane >> 4) * 16;
    uint32_t b_rb[2], b_sw[2];
#pragma unroll
    for (int jn = 0; jn < 2; ++jn) {
        int row = wn0 + jn * 16 + (lane & 7) + ((lane >> 4) << 3);
        b_rb[jn] = row * 128;
        b_sw[jn] = (row & 7) * 16;
    }
    const uint32_t b_kb = ((lane >> 3) & 1) * 16;

    load_tile_cp(sbase, SA0, A,  bm, 0, tid);
    load_tile_cp(sbase, SB0, Bt, bn, 0, tid);
    CP_COMMIT();

    for (int i = 0; i < GK_NC; ++i) {
        const uint32_t aoff = (i & 1) ? SA1 : SA0;
        const uint32_t boff = (i & 1) ? SB1 : SB0;
        if (i + 1 < GK_NC) {
            load_tile_cp(sbase, (i & 1) ? SA0 : SA1, A,  bm, (i + 1) * 64, tid);
            load_tile_cp(sbase, (i & 1) ? SB0 : SB1, Bt, bn, (i + 1) * 64, tid);
            CP_COMMIT();
            CP_WAIT(1);
        } else {
            CP_WAIT(0);
        }
        __syncthreads();

#pragma unroll
        for (int ks = 0; ks < 4; ++ks) {
            const uint32_t kb = ks * 32;
            uint32_t af[4][4];
#pragma unroll
            for (int im = 0; im < 4; ++im)
                ldm_x4(af[im][0], af[im][1], af[im][2], af[im][3],
                       sbase + aoff + a_rb[im] + ((kb + a_kb) ^ a_sw[im]));
            uint32_t bf[4][2];
#pragma unroll
            for (int jn = 0; jn < 2; ++jn) {
                uint32_t r0, r1, r2, r3;
                ldm_x4(r0, r1, r2, r3,
                       sbase + boff + b_rb[jn] + ((kb + b_kb) ^ b_sw[jn]));
                bf[jn * 2][0] = r0; bf[jn * 2][1] = r1;
                bf[jn * 2 + 1][0] = r2; bf[jn * 2 + 1][1] = r3;
            }
#pragma unroll
            for (int im = 0; im < 4; ++im)
#pragma unroll
                for (int jt = 0; jt < 4; ++jt)
                    mma16816(d[im][jt], af[im], bf[jt][0], bf[jt][1]);
        }
        __syncthreads();
    }

    if (outH == nullptr) {
#pragma unroll
        for (int jt = 0; jt < 4; ++jt) {
            const int c0 = bn + wn0 + jt * 8 + 2 * (lane & 3);
            float2 bb = *reinterpret_cast<const float2*>(bias + c0);
#pragma unroll
            for (int im = 0; im < 4; ++im) {
                const int r0 = bm + wm0 + im * 16 + (lane >> 2);
                float2 o0 = make_float2(d[im][jt][0] + bb.x, d[im][jt][1] + bb.y);
                float2 o1 = make_float2(d[im][jt][2] + bb.x, d[im][jt][3] + bb.y);
                *reinterpret_cast<float2*>(C + (size_t)r0 * AD + c0)       = o0;
                *reinterpret_cast<float2*>(C + (size_t)(r0 + 8) * AD + c0) = o1;
            }
        }
    } else {
        // fp16 head-plane epilogue: [(b*NH+h)][L][64]
#pragma unroll
        for (int jt = 0; jt < 4; ++jt) {
            const int c0 = bn + wn0 + jt * 8 + 2 * (lane & 3);
            float2 bb = *reinterpret_cast<const float2*>(bias + c0);
            const int hh = c0 >> 6, dd = c0 & 63;
#pragma unroll
            for (int im = 0; im < 4; ++im) {
                const int r0 = bm + wm0 + im * 16 + (lane >> 2);
#pragma unroll
                for (int half = 0; half < 2; ++half) {
                    const int r = r0 + half * 8;
                    float v0 = (d[im][jt][half * 2 + 0] + bb.x) * oscale;
                    float v1 = (d[im][jt][half * 2 + 1] + bb.y) * oscale;
                    size_t addr = ((size_t)((r >> 11) * NH + hh) * LL + (r & 2047)) * HD + dd;
                    *reinterpret_cast<uint32_t*>(outH + addr) =
                        pack_h2(__float2half_rn(v0), __float2half_rn(v1));
                }
            }
        }
    }
}

// Fused QKV wrapper: blockIdx.z in {0,1,2} selects the projection.
struct QkvArgs {
    const __half* A;        // g_acts base
    const __half* W;        // g_wt base
    const float*  bias[3];
    __half*       outH;     // g_heads base
};

__global__ __launch_bounds__(256, 2)
void gemm_qkv(QkvArgs a)
{
    extern __shared__ char smem[];
    const int z = blockIdx.z;
    const float oscale = (z == 0) ? 0.125f : 1.0f;
    gemm_body(a.A + (size_t)z * MM * AD,
              a.W + (size_t)z * AD * AD,
              a.bias[z],
              nullptr,
              a.outH + (size_t)z * MM * AD,
              oscale, smem);
}

__global__ __launch_bounds__(256, 2)
void gemm_out(const __half* __restrict__ A, const __half* __restrict__ Bt,
              const float* __restrict__ bias, float* __restrict__ C)
{
    extern __shared__ char smem[];
    gemm_body(A, Bt, bias, C, nullptr, 1.0f, smem);
}

// ---------------------------------------------------------------------------
// fp16 mma flash attention (unchanged from R8).
// CTA = 64 q-rows x (head, batch); 128 threads / 4 warps; warp owns 16 rows.
// ---------------------------------------------------------------------------
#define AT_Q   0
#define AT_BUF 8192                     // + buf*32768 ; Kh at +0, Vh at +16384
#define AT_SMEM (8192 + 2*32768)        // 73728

__device__ __forceinline__ void at_load_plane(uint32_t sb, uint32_t soff,
                                              const __half* __restrict__ g,
                                              size_t pbase, int row0, int nrows, int tid)
{
    const int iters = nrows / 16;
#pragma unroll
    for (int i = 0; i < 8; ++i) {
        if (i >= iters) break;
        int idx = i * 128 + tid;
        int r = idx >> 3, seg = idx & 7;
        const char* src = (const char*)(g + pbase + (size_t)(row0 + r) * HD) + seg * 16;
        uint32_t dst = sb + soff + r * 128 + ((seg * 16) ^ ((r & 7) * 16));
        asm volatile("cp.async.cg.shared.global [%0], [%1], 16;" :: "r"(dst), "l"(src));
    }
}

__global__ __launch_bounds__(128, 3)
void attn_mma(const __half* __restrict__ Qh,
              const __half* __restrict__ Kh,
              const __half* __restrict__ Vh,
              __half* __restrict__ Oatt)
{
    extern __shared__ char smem[];
    const uint32_t sb = smem_u32(smem);
    const int tid  = threadIdx.x;
    const int warp = tid >> 5;
    const int lane = tid & 31;
    const int gidr = lane >> 2;
    const int tg   = lane & 3;

    const int qt = blockIdx.x, h = blockIdx.y, b = blockIdx.z;
    const size_t pbase = (size_t)(b * NH + h) * LL * HD;
    const int q0 = qt * 64;

    at_load_plane(sb, AT_Q, Qh, pbase, q0, 64, tid);
    CP_COMMIT();
    at_load_plane(sb, AT_BUF,         Kh, pbase, 0, 128, tid);
    at_load_plane(sb, AT_BUF + 16384, Vh, pbase, 0, 128, tid);
    CP_COMMIT();
    at_load_plane(sb, AT_BUF + 32768, Kh, pbase, 128, 128, tid);
    at_load_plane(sb, AT_BUF + 49152, Vh, pbase, 128, 128, tid);
    CP_COMMIT();

    const uint32_t a_row = 16 * warp + (lane & 15);
    const uint32_t a_off = a_row * 128;
    const uint32_t a_sw  = (a_row & 7) * 16;
    const uint32_t a_kb  = (lane >> 4) * 16;
    const uint32_t b_rowb = (lane & 7) + ((lane >> 4) << 3);
    const uint32_t b_kb   = ((lane >> 3) & 1) * 16;
    const uint32_t v_rowb = (lane & 15);
    const uint32_t v_cb   = (lane >> 4) * 16;

    float m0 = -1e30f, m1 = -1e30f, l0 = 0.f, l1 = 0.f;
    float O[8][4];
#pragma unroll
    for (int j = 0; j < 8; ++j)
#pragma unroll
        for (int q = 0; q < 4; ++q) O[j][q] = 0.f;

    for (int ci = 0; ci < 16; ++ci) {
        if (ci < 15) { CP_WAIT(1); } else { CP_WAIT(0); }
        __syncthreads();

        const uint32_t kh_ = sb + AT_BUF + (ci & 1) * 32768;
        const uint32_t vh_ = kh_ + 16384;

        // ---- S = Q K^T ----
        float s[16][4];
#pragma unroll
        for (int j = 0; j < 16; ++j)
#pragma unroll
            for (int q = 0; q < 4; ++q) s[j][q] = 0.f;

#pragma unroll
        for (int ks = 0; ks < 4; ++ks) {
            const uint32_t kb = ks * 32;
            uint32_t af[4];
            ldm_x4(af[0], af[1], af[2], af[3], sb + AT_Q + a_off + ((kb + a_kb) ^ a_sw));
#pragma unroll
            for (int jj = 0; jj < 8; ++jj) {
                uint32_t row = 16 * jj + b_rowb;
                uint32_t r0, r1, r2, r3;
                ldm_x4(r0, r1, r2, r3, kh_ + row * 128 + ((kb + b_kb) ^ ((row & 7) * 16)));
                mma16816(s[2 * jj],     af, r0, r1);
                mma16816(s[2 * jj + 1], af, r2, r3);
            }
        }

        // ---- online softmax ----
        float cm0 = -1e30f, cm1 = -1e30f;
#pragma unroll
        for (int j = 0; j < 16; ++j) {
            cm0 = fmaxf(cm0, fmaxf(s[j][0], s[j][1]));
            cm1 = fmaxf(cm1, fmaxf(s[j][2], s[j][3]));
        }
        cm0 = fmaxf(cm0, __shfl_xor_sync(0xffffffffu, cm0, 1));
        cm0 = fmaxf(cm0, __shfl_xor_sync(0xffffffffu, cm0, 2));
        cm1 = fmaxf(cm1, __shfl_xor_sync(0xffffffffu, cm1, 1));
        cm1 = fmaxf(cm1, __shfl_xor_sync(0xffffffffu, cm1, 2));
        const float mn0 = fmaxf(m0, cm0);
        const float mn1 = fmaxf(m1, cm1);
        const float corr0 = __expf(m0 - mn0);
        const float corr1 = __expf(m1 - mn1);
        m0 = mn0; m1 = mn1;
#pragma unroll
        for (int j = 0; j < 8; ++j) {
            O[j][0] *= corr0; O[j][1] *= corr0;
            O[j][2] *= corr1; O[j][3] *= corr1;
        }
        l0 *= corr0; l1 *= corr1;

        float rs0 = 0.f, rs1 = 0.f;

#pragma unroll
        for (int kk = 0; kk < 8; ++kk) {
            float p00 = __expf(s[2*kk][0]   - mn0);
            float p01 = __expf(s[2*kk][1]   - mn0);
            float p02 = __expf(s[2*kk][2]   - mn1);
            float p03 = __expf(s[2*kk][3]   - mn1);
            float p10 = __expf(s[2*kk+1][0] - mn0);
            float p11 = __expf(s[2*kk+1][1] - mn0);
            float p12 = __expf(s[2*kk+1][2] - mn1);
            float p13 = __expf(s[2*kk+1][3] - mn1);
            rs0 += (p00 + p01) + (p10 + p11);
            rs1 += (p02 + p03) + (p12 + p13);

            uint32_t ah[4];
            ah[0] = pack_h2(__float2half_rn(p00), __float2half_rn(p01));
            ah[1] = pack_h2(__float2half_rn(p02), __float2half_rn(p03));
            ah[2] = pack_h2(__float2half_rn(p10), __float2half_rn(p11));
            ah[3] = pack_h2(__float2half_rn(p12), __float2half_rn(p13));

            const uint32_t vrow = 16 * kk + v_rowb;
            const uint32_t vsw  = (vrow & 7) * 16;
            uint32_t vhf[8][2];
#pragma unroll
            for (int nb = 0; nb < 4; ++nb) {
                const uint32_t col = (nb * 32 + v_cb) ^ vsw;
                uint32_t r0, r1, r2, r3;
                ldm_x4_t(r0, r1, r2, r3, vh_ + vrow * 128 + col);
                vhf[2*nb][0] = r0;   vhf[2*nb][1] = r1;
                vhf[2*nb+1][0] = r2; vhf[2*nb+1][1] = r3;
            }
#pragma unroll
            for (int jf = 0; jf < 8; ++jf)
                mma16816(O[jf], ah, vhf[jf][0], vhf[jf][1]);
        }

        rs0 += __shfl_xor_sync(0xffffffffu, rs0, 1);
        rs0 += __shfl_xor_sync(0xffffffffu, rs0, 2);
        rs1 += __shfl_xor_sync(0xffffffffu, rs1, 1);
        rs1 += __shfl_xor_sync(0xffffffffu, rs1, 2);
        l0 += rs0; l1 += rs1;

        __syncthreads();
        if (ci + 2 < 16) {
            uint32_t bb = AT_BUF + (ci & 1) * 32768;
            int row0 = (ci + 2) * 128;
            at_load_plane(sb, bb,         Kh, pbase, row0, 128, tid);
            at_load_plane(sb, bb + 16384, Vh, pbase, row0, 128, tid);
            CP_COMMIT();
        }
    }

    const float inv0 = 1.f / l0;
    const float inv1 = 1.f / l1;
    const int colb = h * HD + 2 * tg;
#pragma unroll
    for (int jf = 0; jf < 8; ++jf) {
#pragma unroll
        for (int half = 0; half < 2; ++half) {
            const int r = 16 * warp + gidr + half * 8;
            const float inv = half ? inv1 : inv0;
            float v0 = O[jf][half * 2 + 0] * inv;
            float v1 = O[jf][half * 2 + 1] * inv;
            size_t addr = (size_t)(b * LL + q0 + r) * AD + colb + 8 * jf;
            *reinterpret_cast<uint32_t*>(Oatt + addr) =
                pack_h2(__float2half_rn(v0), __float2half_rn(v1));
        }
    }
}

// ---------------------------------------------------------------------------
// Launch: 5 kernels total
// ---------------------------------------------------------------------------
extern "C" void kernel_launch(void* const* d_in, const int* in_sizes, int n_in,
                              void* d_out, int out_size)
{
    const float* query = (const float*)d_in[0];
    const float* key   = (const float*)d_in[1];
    const float* value = (const float*)d_in[2];
    const float* Wq = (const float*)d_in[3];
    const float* bq = (const float*)d_in[4];
    const float* Wk = (const float*)d_in[5];
    const float* bk = (const float*)d_in[6];
    const float* Wv = (const float*)d_in[7];
    const float* bv = (const float*)d_in[8];
    const float* Wo = (const float*)d_in[9];
    const float* bo = (const float*)d_in[10];
    float* out = (float*)d_out;

    __half *pacts, *pwt, *pheads, *pao;
    cudaGetSymbolAddress((void**)&pacts,  g_acts);
    cudaGetSymbolAddress((void**)&pwt,    g_wt);
    cudaGetSymbolAddress((void**)&pheads, g_heads);
    cudaGetSymbolAddress((void**)&pao,    g_ao);

    cudaFuncSetAttribute(gemm_qkv, cudaFuncAttributeMaxDynamicSharedMemorySize, G_SMEM);
    cudaFuncSetAttribute(gemm_out, cudaFuncAttributeMaxDynamicSharedMemorySize, G_SMEM);
    cudaFuncSetAttribute(attn_mma, cudaFuncAttributeMaxDynamicSharedMemorySize, AT_SMEM);

    // 1) all weight transposes (independent)
    dim3 wgrid(32, 32, 4), wblk(32, 8);
    conv_wt4<<<wgrid, wblk>>>(Wq, Wk, Wv, Wo, pwt);

    // 2) all activation conversions (independent)
    dim3 cgrid(MM, 3);
    conv_act3<<<cgrid, 256>>>(query, key, value, pacts);

    // 3) fused QKV projection GEMM (1536 CTAs, one wave train)
    QkvArgs qa;
    qa.A = pacts; qa.W = pwt; qa.outH = pheads;
    qa.bias[0] = bq; qa.bias[1] = bk; qa.bias[2] = bv;
    dim3 ggrid(AD / 128, MM / 128, 3);   // (8, 64, 3)
    gemm_qkv<<<ggrid, 256, G_SMEM>>>(qa);

    // 4) attention
    dim3 agrid(LL / 64, NH, BB);         // (32, 16, 4)
    attn_mma<<<agrid, 128, AT_SMEM>>>(pheads,
                                      pheads + (size_t)MM * AD,
                                      pheads + 2 * (size_t)MM * AD,
                                      pao);

    // 5) output projection
    dim3 ogrid(AD / 128, MM / 128);      // (8, 64)
    gemm_out<<<ogrid, 256, G_SMEM>>>(pao, pwt + 3 * (size_t)AD * AD, bo, out);
}